// round 10
// baseline (speedup 1.0000x reference)
#include <cuda_runtime.h>
#include <cuda_bf16.h>
#include <cstdint>

#define N_NODES 50000
#define N_EDGES 800000
#define IN_DIM  128
#define HID_DIM 128
#define OUT_DIM 64

#define SCAN_BS   512
#define SCAN_NB   ((N_NODES + SCAN_BS - 1) / SCAN_BS)   // 98
#define HALF_NODES 25088                                 // 196 * 128 (gemm tile aligned)

// ---------------- scratch (device globals: no allocation allowed) -------------
// Only referenced from DEVICE code (host-side use of __device__ symbols gives
// the host shadow address -> silent ATS writes to host RAM; R5 bug).
__device__ __align__(16) int                g_degi    [N_NODES];
__device__ __align__(16) float              g_dinv    [N_NODES];
__device__ __align__(16) int                g_rowstart[N_NODES + 1];
__device__ __align__(16) int                g_rank    [N_EDGES];   // edge rank within dst
__device__ __align__(16) int                g_csr     [N_EDGES];   // src per CSR slot
__device__ __align__(16) unsigned long long g_state   [SCAN_NB];   // lookback states
__device__ __align__(16) float              g_xw      [N_NODES * HID_DIM];  // x@W1 (unscaled)
__device__ __align__(16) float              g_h       [N_NODES * HID_DIM];  // layer-1 out
__device__ __align__(16) float              g_hw      [N_NODES * OUT_DIM];  // (h@W2)*dinv

// ---------------- packed f32x2 helpers -----------------------------------------
__device__ __forceinline__ unsigned long long pack2(float lo, float hi) {
    unsigned long long r;
    asm("mov.b64 %0, {%1, %2};" : "=l"(r)
        : "r"(__float_as_uint(lo)), "r"(__float_as_uint(hi)));
    return r;
}
__device__ __forceinline__ void unpack2(unsigned long long v, float& lo, float& hi) {
    unsigned a, b;
    asm("mov.b64 {%0, %1}, %2;" : "=r"(a), "=r"(b) : "l"(v));
    lo = __uint_as_float(a); hi = __uint_as_float(b);
}
__device__ __forceinline__ void ffma2(unsigned long long& d,
                                      unsigned long long a, unsigned long long b) {
    asm("fma.rn.f32x2 %0, %1, %2, %0;" : "+l"(d) : "l"(a), "l"(b));
}

// ---------------- zero: degrees + lookback states ------------------------------
__global__ void zero_kernel() {
    int i = blockIdx.x * blockDim.x + threadIdx.x;
    if (i < N_NODES) g_degi[i] = 0;
    if (i < SCAN_NB) g_state[i] = 0ull;
}

// ---------------- degree + per-edge rank (atomic return reused) ----------------
__global__ void deg_kernel(const int* __restrict__ dst) {
    int e4 = (blockIdx.x * blockDim.x + threadIdx.x) * 4;
    if (e4 + 3 < N_EDGES) {
        int4 d = *(const int4*)&dst[e4];
        int4 r;
        r.x = ((unsigned)d.x < N_NODES) ? atomicAdd(&g_degi[d.x], 1) : 0;
        r.y = ((unsigned)d.y < N_NODES) ? atomicAdd(&g_degi[d.y], 1) : 0;
        r.z = ((unsigned)d.z < N_NODES) ? atomicAdd(&g_degi[d.z], 1) : 0;
        r.w = ((unsigned)d.w < N_NODES) ? atomicAdd(&g_degi[d.w], 1) : 0;
        *(int4*)&g_rank[e4] = r;
    } else {
        for (int e = e4; e < N_EDGES; e++) {
            unsigned d = (unsigned)dst[e];
            g_rank[e] = (d < N_NODES) ? atomicAdd(&g_degi[d], 1) : 0;
        }
    }
}

// ---------------- single-pass scan (decoupled lookback) + fused dinv -----------
// 98 blocks <= 148 SMs: all co-resident, spin-lookback is deadlock-free.
// state[b] = flag<<32 | value ; flag: 0=invalid, 1=partial, 2=inclusive.
__global__ void scan_kernel() {
    __shared__ int sm[SCAN_BS];
    __shared__ int s_excl;
    int t = threadIdx.x, b = blockIdx.x;
    int i = b * SCAN_BS + t;
    int s = (i < N_NODES) ? g_degi[i] : 0;
    if (i < N_NODES) g_dinv[i] = rsqrtf((float)s + 1.0f);   // fused dinv
    sm[t] = s;
    __syncthreads();
    #pragma unroll
    for (int off = 1; off < SCAN_BS; off <<= 1) {
        int v = (t >= off) ? sm[t - off] : 0;
        __syncthreads();
        sm[t] += v;
        __syncthreads();
    }
    int total = sm[SCAN_BS - 1];

    if (t == 0) {
        if (b == 0) {
            atomicExch(&g_state[0], (2ull << 32) | (unsigned)total);
            s_excl = 0;
        } else {
            atomicExch(&g_state[b], (1ull << 32) | (unsigned)total);
            int excl = 0;
            int idx = b - 1;
            while (true) {
                unsigned long long st = atomicAdd(&g_state[idx], 0ull);  // atomic read
                unsigned flag = (unsigned)(st >> 32);
                if (flag == 0u) { __nanosleep(20); continue; }
                excl += (int)(unsigned)st;
                if (flag == 2u) break;
                idx--;
            }
            atomicExch(&g_state[b], (2ull << 32) | (unsigned)(excl + total));
            s_excl = excl;
        }
    }
    __syncthreads();
    if (i < N_NODES) g_rowstart[i] = sm[t] - s + s_excl;   // exclusive prefix
    if (i == 0) g_rowstart[N_NODES] = N_EDGES;
}

// ---------------- CSR fill: atomic-free (slot = rowstart[d] + rank[e]) ---------
__global__ void fill_kernel(const int* __restrict__ src, const int* __restrict__ dst) {
    int e4 = (blockIdx.x * blockDim.x + threadIdx.x) * 4;
    if (e4 + 3 < N_EDGES) {
        int4 d = *(const int4*)&dst[e4];
        int4 s = *(const int4*)&src[e4];
        int4 r = *(const int4*)&g_rank[e4];
        if ((unsigned)d.x < N_NODES && (unsigned)s.x < N_NODES)
            g_csr[g_rowstart[d.x] + r.x] = s.x;
        if ((unsigned)d.y < N_NODES && (unsigned)s.y < N_NODES)
            g_csr[g_rowstart[d.y] + r.y] = s.y;
        if ((unsigned)d.z < N_NODES && (unsigned)s.z < N_NODES)
            g_csr[g_rowstart[d.z] + r.z] = s.z;
        if ((unsigned)d.w < N_NODES && (unsigned)s.w < N_NODES)
            g_csr[g_rowstart[d.w] + r.w] = s.w;
    } else {
        for (int e = e4; e < N_EDGES; e++) {
            unsigned d = (unsigned)dst[e], s = (unsigned)src[e];
            if (d < N_NODES && s < N_NODES)
                g_csr[g_rowstart[d] + g_rank[e]] = (int)s;
        }
    }
}

// ---------------- SGEMM: 128xBN tile, FFMA2 microkernel ------------------------
template <int BN, bool SCALE_DINV>
__device__ __forceinline__ void sgemm_body(const float* __restrict__ A,
                                           const float* __restrict__ B,
                                           float* __restrict__ C, int M, int rowbase) {
    constexpr int BM = 128, BK = 16, KD = 128;
    constexpr int TN = (BN == 128) ? 8 : 4;
    __shared__ float As[BK][BM];                // transposed A tile
    __shared__ float Bs[BK][BN];

    const int tid = threadIdx.x;                // 256 threads
    const int tx = tid & 15;
    const int ty = tid >> 4;
    const int row0 = rowbase + blockIdx.y * BM;

    unsigned long long acc2[4][TN] = {};        // [row-pair][col]

    for (int k0 = 0; k0 < KD; k0 += BK) {
        {
            int idx = tid * 8;
            int m = idx >> 4, kk = idx & 15;    // kk in {0, 8}
            int r = row0 + m;
            float4 f0 = make_float4(0.f, 0.f, 0.f, 0.f), f1 = f0;
            if (r < M) {
                f0 = *(const float4*)&A[(size_t)r * KD + k0 + kk];
                f1 = *(const float4*)&A[(size_t)r * KD + k0 + kk + 4];
            }
            As[kk + 0][m] = f0.x; As[kk + 1][m] = f0.y;
            As[kk + 2][m] = f0.z; As[kk + 3][m] = f0.w;
            As[kk + 4][m] = f1.x; As[kk + 5][m] = f1.y;
            As[kk + 6][m] = f1.z; As[kk + 7][m] = f1.w;
        }
        if constexpr (BN == 128) {
            int idx = tid * 8;
            int kb = idx >> 7, n = idx & 127;
            const float* bp = &B[(size_t)(k0 + kb) * BN + n];
            *(float4*)&Bs[kb][n]     = *(const float4*)bp;
            *(float4*)&Bs[kb][n + 4] = *(const float4*)(bp + 4);
        } else {
            int idx = tid * 4;
            int kb = idx >> 6, n = idx & 63;
            *(float4*)&Bs[kb][n] = *(const float4*)&B[(size_t)(k0 + kb) * BN + n];
        }
        __syncthreads();

        #pragma unroll
        for (int k = 0; k < BK; k++) {
            float a[8];
            *(float4*)&a[0] = *(const float4*)&As[k][ty * 8];
            *(float4*)&a[4] = *(const float4*)&As[k][ty * 8 + 4];
            float b[TN];
            *(float4*)&b[0] = *(const float4*)&Bs[k][tx * 4];
            if constexpr (BN == 128)
                *(float4*)&b[4] = *(const float4*)&Bs[k][64 + tx * 4];

            unsigned long long a2[4];
            #pragma unroll
            for (int p = 0; p < 4; p++) a2[p] = pack2(a[2 * p], a[2 * p + 1]);
            unsigned long long b2[TN];
            #pragma unroll
            for (int j = 0; j < TN; j++) b2[j] = pack2(b[j], b[j]);

            #pragma unroll
            for (int p = 0; p < 4; p++)
                #pragma unroll
                for (int j = 0; j < TN; j++)
                    ffma2(acc2[p][j], a2[p], b2[j]);
        }
        __syncthreads();
    }

    #pragma unroll
    for (int p = 0; p < 4; p++) {
        int r0 = row0 + ty * 8 + 2 * p;
        if (r0 >= M) continue;
        float s0 = 1.f, s1 = 1.f;
        if constexpr (SCALE_DINV) {
            s0 = g_dinv[r0];
            s1 = (r0 + 1 < M) ? g_dinv[r0 + 1] : 0.f;
        }
        float v0[TN], v1[TN];
        #pragma unroll
        for (int j = 0; j < TN; j++) {
            float lo, hi;
            unpack2(acc2[p][j], lo, hi);
            v0[j] = lo * s0; v1[j] = hi * s1;
        }
        *(float4*)&C[(size_t)r0 * BN + tx * 4] = *(float4*)&v0[0];
        if (r0 + 1 < M)
            *(float4*)&C[(size_t)(r0 + 1) * BN + tx * 4] = *(float4*)&v1[0];
        if constexpr (BN == 128) {
            *(float4*)&C[(size_t)r0 * BN + 64 + tx * 4] = *(float4*)&v0[4];
            if (r0 + 1 < M)
                *(float4*)&C[(size_t)(r0 + 1) * BN + 64 + tx * 4] = *(float4*)&v1[4];
        }
    }
}

__global__ void gemm1_kernel(const float* __restrict__ x, const float* __restrict__ W1) {
    sgemm_body<HID_DIM, false>(x, W1, g_xw, N_NODES, 0);
}
__global__ void gemm2_kernel(const float* __restrict__ W2, int rowbase, int rowlim) {
    sgemm_body<OUT_DIM, true>(g_h, W2, g_hw, rowlim, rowbase);
}

// ---------------- gather layer 1: warp per node, 8x unrolled, per-edge dinv ----
// h[d] = relu( dinv[d] * ( sum_s xw[s]*dinv[s] + xw[d]*dinv[d] ) + b1 )
__global__ void gather1_kernel(const float* __restrict__ b1, int base, int count) {
    int wi = (blockIdx.x * blockDim.x + threadIdx.x) >> 5;
    int lane = threadIdx.x & 31;
    if (wi >= count) return;
    int w = base + wi;
    int beg = g_rowstart[w];
    int end = g_rowstart[w + 1];
    const float4* xw4 = reinterpret_cast<const float4*>(g_xw);

    float dself = g_dinv[w];
    float4 self = xw4[(size_t)w * 32 + lane];
    float4 acc;
    acc.x = self.x * dself; acc.y = self.y * dself;
    acc.z = self.z * dself; acc.w = self.w * dself;

    int e = beg;
    for (; e + 7 < end; e += 8) {
        int sI[8]; float dv[8]; float4 v[8];
        #pragma unroll
        for (int i = 0; i < 8; i++) sI[i] = __ldg(&g_csr[e + i]);
        #pragma unroll
        for (int i = 0; i < 8; i++) dv[i] = __ldg(&g_dinv[sI[i]]);
        #pragma unroll
        for (int i = 0; i < 8; i++) v[i] = __ldg(&xw4[(size_t)sI[i] * 32 + lane]);
        #pragma unroll
        for (int i = 0; i < 8; i++) {
            acc.x = fmaf(v[i].x, dv[i], acc.x);
            acc.y = fmaf(v[i].y, dv[i], acc.y);
            acc.z = fmaf(v[i].z, dv[i], acc.z);
            acc.w = fmaf(v[i].w, dv[i], acc.w);
        }
    }
    for (; e < end; e++) {
        int s0 = __ldg(&g_csr[e]);
        float d0 = __ldg(&g_dinv[s0]);
        float4 v0 = __ldg(&xw4[(size_t)s0 * 32 + lane]);
        acc.x = fmaf(v0.x, d0, acc.x); acc.y = fmaf(v0.y, d0, acc.y);
        acc.z = fmaf(v0.z, d0, acc.z); acc.w = fmaf(v0.w, d0, acc.w);
    }
    float4 bb = reinterpret_cast<const float4*>(b1)[lane];
    float4 r;
    r.x = fmaxf(fmaf(dself, acc.x, bb.x), 0.f);
    r.y = fmaxf(fmaf(dself, acc.y, bb.y), 0.f);
    r.z = fmaxf(fmaf(dself, acc.z, bb.z), 0.f);
    r.w = fmaxf(fmaf(dself, acc.w, bb.w), 0.f);
    reinterpret_cast<float4*>(g_h)[(size_t)w * 32 + lane] = r;
}

// ---------------- gather layer 2 + FC + leaky, fully fused, 8x unrolled --------
__global__ void gather2_kernel(const float* __restrict__ b2,
                               const float* __restrict__ Wfc,
                               const float* __restrict__ bfc,
                               float* __restrict__ out) {
    int w = (blockIdx.x * blockDim.x + threadIdx.x) >> 5;
    int lane = threadIdx.x & 31;
    if (w >= N_NODES) return;
    int beg = g_rowstart[w];
    int end = g_rowstart[w + 1];
    const float2* hw2 = reinterpret_cast<const float2*>(g_hw);   // 32 float2/row

    float2 acc = hw2[(size_t)w * 32 + lane];    // self term (hw' already scaled)
    int e = beg;
    for (; e + 7 < end; e += 8) {
        int sI[8]; float2 v[8];
        #pragma unroll
        for (int i = 0; i < 8; i++) sI[i] = __ldg(&g_csr[e + i]);
        #pragma unroll
        for (int i = 0; i < 8; i++) v[i] = __ldg(&hw2[(size_t)sI[i] * 32 + lane]);
        #pragma unroll
        for (int i = 0; i < 8; i++) { acc.x += v[i].x; acc.y += v[i].y; }
    }
    for (; e < end; e++) {
        int s0 = __ldg(&g_csr[e]);
        float2 v0 = __ldg(&hw2[(size_t)s0 * 32 + lane]);
        acc.x += v0.x; acc.y += v0.y;
    }
    float di = g_dinv[w];
    float2 b2v = reinterpret_cast<const float2*>(b2)[lane];
    float vx = di * acc.x + b2v.x;              // feature 2*lane
    float vy = di * acc.y + b2v.y;              // feature 2*lane+1

    int f0 = 2 * lane, f1 = 2 * lane + 1;
    float p0 = vx * __ldg(&Wfc[f0 * 2 + 0]) + vy * __ldg(&Wfc[f1 * 2 + 0]);
    float p1 = vx * __ldg(&Wfc[f0 * 2 + 1]) + vy * __ldg(&Wfc[f1 * 2 + 1]);
    #pragma unroll
    for (int off = 16; off > 0; off >>= 1) {
        p0 += __shfl_xor_sync(0xffffffff, p0, off);
        p1 += __shfl_xor_sync(0xffffffff, p1, off);
    }
    if (lane == 0) {
        float o0 = p0 + __ldg(&bfc[0]);
        float o1 = p1 + __ldg(&bfc[1]);
        out[w * 2 + 0] = (o0 > 0.f) ? o0 : 0.01f * o0;
        out[w * 2 + 1] = (o1 > 0.f) ? o1 : 0.01f * o1;
    }
}

// ---------------- launch -------------------------------------------------------
// Fork-join 1: gemm1 overlaps the degree/CSR chain.
// Fork-join 2: gemm2(chunk0) overlaps gather1(chunk1).
extern "C" void kernel_launch(void* const* d_in, const int* in_sizes, int n_in,
                              void* d_out, int out_size) {
    const float* x   = (const float*)d_in[0];
    const int*   ei  = (const int*)d_in[1];   // JAX default: int64 demoted to int32
    const float* W1  = (const float*)d_in[2];
    const float* b1  = (const float*)d_in[3];
    const float* W2  = (const float*)d_in[4];
    const float* b2  = (const float*)d_in[5];
    const float* Wfc = (const float*)d_in[6];
    const float* bfc = (const float*)d_in[7];
    float* out = (float*)d_out;

    const int* src = ei;
    const int* dst = ei + N_EDGES;

    static cudaStream_t s_side = nullptr;
    static cudaEvent_t  e_fork = nullptr, e_join = nullptr;
    static cudaEvent_t  e_g1a = nullptr, e_g1b = nullptr, e_mm2 = nullptr;
    if (s_side == nullptr) {
        cudaStreamCreateWithFlags(&s_side, cudaStreamNonBlocking);
        cudaEventCreateWithFlags(&e_fork, cudaEventDisableTiming);
        cudaEventCreateWithFlags(&e_join, cudaEventDisableTiming);
        cudaEventCreateWithFlags(&e_g1a,  cudaEventDisableTiming);
        cudaEventCreateWithFlags(&e_g1b,  cudaEventDisableTiming);
        cudaEventCreateWithFlags(&e_mm2,  cudaEventDisableTiming);
    }

    const int EDGE_T4 = (N_EDGES / 4 + 255) / 256;   // 4 edges per thread

    // fork side stream off the (captured) default stream
    cudaEventRecord(e_fork, 0);
    cudaStreamWaitEvent(s_side, e_fork, 0);

    // side stream: degree(+rank) + dinv + scan + atomic-free fill
    zero_kernel<<<(N_NODES + 255) / 256, 256, 0, s_side>>>();
    deg_kernel<<<EDGE_T4, 256, 0, s_side>>>(dst);
    scan_kernel<<<SCAN_NB, SCAN_BS, 0, s_side>>>();   // single-pass + dinv
    fill_kernel<<<EDGE_T4, 256, 0, s_side>>>(src, dst);
    cudaEventRecord(e_join, s_side);

    // default stream: gemm1 (independent of degree chain), then join
    gemm1_kernel<<<dim3(1, (N_NODES + 127) / 128), 256>>>(x, W1);
    cudaStreamWaitEvent(0, e_join, 0);

    // layer-1 aggregation split into two chunks; gemm2 pipelines behind them
    const int C0 = HALF_NODES, C1 = N_NODES - HALF_NODES;
    gather1_kernel<<<(C0 * 32 + 255) / 256, 256>>>(b1, 0, C0);
    cudaEventRecord(e_g1a, 0);
    gather1_kernel<<<(C1 * 32 + 255) / 256, 256>>>(b1, C0, C1);
    cudaEventRecord(e_g1b, 0);

    // side stream: gemm2 chunk0 overlaps gather1 chunk1
    cudaStreamWaitEvent(s_side, e_g1a, 0);
    gemm2_kernel<<<dim3(1, C0 / 128), 256, 0, s_side>>>(W2, 0, C0);
    cudaStreamWaitEvent(s_side, e_g1b, 0);
    gemm2_kernel<<<dim3(1, (C1 + 127) / 128), 256, 0, s_side>>>(W2, C0, N_NODES);
    cudaEventRecord(e_mm2, s_side);

    // fc + leaky relu (needs all of g_hw)
    cudaStreamWaitEvent(0, e_mm2, 0);
    gather2_kernel<<<(N_NODES * 32 + 255) / 256, 256>>>(b2, Wfc, bfc, out);
}

// round 11
// speedup vs baseline: 1.2025x; 1.2025x over previous
#include <cuda_runtime.h>
#include <cuda_bf16.h>
#include <cstdint>

#define N_NODES 50000
#define N_EDGES 800000
#define IN_DIM  128
#define HID_DIM 128
#define OUT_DIM 64

#define SCAN_BS   512
#define SCAN_NB   ((N_NODES + SCAN_BS - 1) / SCAN_BS)   // 98

// ---------------- scratch (device globals: no allocation allowed) -------------
// Only referenced from DEVICE code (host-side use of __device__ symbols gives
// the host shadow address -> silent ATS writes to host RAM; R5 bug).
__device__ __align__(16) int                g_degi    [N_NODES];
__device__ __align__(16) float              g_dinv    [N_NODES];
__device__ __align__(16) int                g_rowstart[N_NODES + 1];
__device__ __align__(16) int                g_rank    [N_EDGES];   // edge rank within dst
__device__ __align__(16) int                g_csr     [N_EDGES];   // src per CSR slot
__device__ __align__(16) unsigned long long g_state   [SCAN_NB];   // lookback states
__device__ __align__(16) float              g_xw      [N_NODES * HID_DIM];  // x@W1 (unscaled)
__device__ __align__(16) float              g_h       [N_NODES * HID_DIM];  // layer-1 out
__device__ __align__(16) float              g_hw      [N_NODES * OUT_DIM];  // (h@W2)*dinv

// ---------------- packed f32x2 helpers -----------------------------------------
__device__ __forceinline__ unsigned long long pack2(float lo, float hi) {
    unsigned long long r;
    asm("mov.b64 %0, {%1, %2};" : "=l"(r)
        : "r"(__float_as_uint(lo)), "r"(__float_as_uint(hi)));
    return r;
}
__device__ __forceinline__ void unpack2(unsigned long long v, float& lo, float& hi) {
    unsigned a, b;
    asm("mov.b64 {%0, %1}, %2;" : "=r"(a), "=r"(b) : "l"(v));
    lo = __uint_as_float(a); hi = __uint_as_float(b);
}
__device__ __forceinline__ void ffma2(unsigned long long& d,
                                      unsigned long long a, unsigned long long b) {
    asm("fma.rn.f32x2 %0, %1, %2, %0;" : "+l"(d) : "l"(a), "l"(b));
}

// ---------------- zero: degrees + lookback states ------------------------------
__global__ void zero_kernel() {
    int i = blockIdx.x * blockDim.x + threadIdx.x;
    if (i < N_NODES) g_degi[i] = 0;
    if (i < SCAN_NB) g_state[i] = 0ull;
}

// ---------------- degree + per-edge rank (1 edge/thread: max MLP) --------------
__global__ void deg_kernel(const int* __restrict__ dst) {
    int e = blockIdx.x * blockDim.x + threadIdx.x;
    if (e >= N_EDGES) return;
    unsigned d = (unsigned)dst[e];
    g_rank[e] = (d < N_NODES) ? atomicAdd(&g_degi[d], 1) : 0;
}

// ---------------- single-pass scan (decoupled lookback) + fused dinv -----------
// 98 blocks <= 148 SMs: all co-resident, spin-lookback is deadlock-free.
// state[b] = flag<<32 | value ; flag: 0=invalid, 1=partial, 2=inclusive.
__global__ void scan_kernel() {
    __shared__ int sm[SCAN_BS];
    __shared__ int s_excl;
    int t = threadIdx.x, b = blockIdx.x;
    int i = b * SCAN_BS + t;
    int s = (i < N_NODES) ? g_degi[i] : 0;
    if (i < N_NODES) g_dinv[i] = rsqrtf((float)s + 1.0f);   // fused dinv
    sm[t] = s;
    __syncthreads();
    #pragma unroll
    for (int off = 1; off < SCAN_BS; off <<= 1) {
        int v = (t >= off) ? sm[t - off] : 0;
        __syncthreads();
        sm[t] += v;
        __syncthreads();
    }
    int total = sm[SCAN_BS - 1];

    if (t == 0) {
        if (b == 0) {
            atomicExch(&g_state[0], (2ull << 32) | (unsigned)total);
            s_excl = 0;
        } else {
            atomicExch(&g_state[b], (1ull << 32) | (unsigned)total);
            int excl = 0;
            int idx = b - 1;
            while (true) {
                unsigned long long st = atomicAdd(&g_state[idx], 0ull);  // atomic read
                unsigned flag = (unsigned)(st >> 32);
                if (flag == 0u) { __nanosleep(20); continue; }
                excl += (int)(unsigned)st;
                if (flag == 2u) break;
                idx--;
            }
            atomicExch(&g_state[b], (2ull << 32) | (unsigned)(excl + total));
            s_excl = excl;
        }
    }
    __syncthreads();
    if (i < N_NODES) g_rowstart[i] = sm[t] - s + s_excl;   // exclusive prefix
    if (i == 0) g_rowstart[N_NODES] = N_EDGES;
}

// ---------------- CSR fill: atomic-free (slot = rowstart[d] + rank[e]) ---------
__global__ void fill_kernel(const int* __restrict__ src, const int* __restrict__ dst) {
    int e4 = (blockIdx.x * blockDim.x + threadIdx.x) * 4;
    if (e4 + 3 < N_EDGES) {
        int4 d = *(const int4*)&dst[e4];
        int4 s = *(const int4*)&src[e4];
        int4 r = *(const int4*)&g_rank[e4];
        if ((unsigned)d.x < N_NODES && (unsigned)s.x < N_NODES)
            g_csr[g_rowstart[d.x] + r.x] = s.x;
        if ((unsigned)d.y < N_NODES && (unsigned)s.y < N_NODES)
            g_csr[g_rowstart[d.y] + r.y] = s.y;
        if ((unsigned)d.z < N_NODES && (unsigned)s.z < N_NODES)
            g_csr[g_rowstart[d.z] + r.z] = s.z;
        if ((unsigned)d.w < N_NODES && (unsigned)s.w < N_NODES)
            g_csr[g_rowstart[d.w] + r.w] = s.w;
    } else {
        for (int e = e4; e < N_EDGES; e++) {
            unsigned d = (unsigned)dst[e], s = (unsigned)src[e];
            if (d < N_NODES && s < N_NODES)
                g_csr[g_rowstart[d] + g_rank[e]] = (int)s;
        }
    }
}

// ---------------- SGEMM: 128xBN tile, FFMA2 microkernel ------------------------
template <int BN, bool SCALE_DINV>
__device__ __forceinline__ void sgemm_body(const float* __restrict__ A,
                                           const float* __restrict__ B,
                                           float* __restrict__ C, int M) {
    constexpr int BM = 128, BK = 16, KD = 128;
    constexpr int TN = (BN == 128) ? 8 : 4;
    __shared__ float As[BK][BM];                // transposed A tile
    __shared__ float Bs[BK][BN];

    const int tid = threadIdx.x;                // 256 threads
    const int tx = tid & 15;
    const int ty = tid >> 4;
    const int row0 = blockIdx.y * BM;

    unsigned long long acc2[4][TN] = {};        // [row-pair][col]

    for (int k0 = 0; k0 < KD; k0 += BK) {
        {
            int idx = tid * 8;
            int m = idx >> 4, kk = idx & 15;    // kk in {0, 8}
            int r = row0 + m;
            float4 f0 = make_float4(0.f, 0.f, 0.f, 0.f), f1 = f0;
            if (r < M) {
                f0 = *(const float4*)&A[(size_t)r * KD + k0 + kk];
                f1 = *(const float4*)&A[(size_t)r * KD + k0 + kk + 4];
            }
            As[kk + 0][m] = f0.x; As[kk + 1][m] = f0.y;
            As[kk + 2][m] = f0.z; As[kk + 3][m] = f0.w;
            As[kk + 4][m] = f1.x; As[kk + 5][m] = f1.y;
            As[kk + 6][m] = f1.z; As[kk + 7][m] = f1.w;
        }
        if constexpr (BN == 128) {
            int idx = tid * 8;
            int kb = idx >> 7, n = idx & 127;
            const float* bp = &B[(size_t)(k0 + kb) * BN + n];
            *(float4*)&Bs[kb][n]     = *(const float4*)bp;
            *(float4*)&Bs[kb][n + 4] = *(const float4*)(bp + 4);
        } else {
            int idx = tid * 4;
            int kb = idx >> 6, n = idx & 63;
            *(float4*)&Bs[kb][n] = *(const float4*)&B[(size_t)(k0 + kb) * BN + n];
        }
        __syncthreads();

        #pragma unroll
        for (int k = 0; k < BK; k++) {
            float a[8];
            *(float4*)&a[0] = *(const float4*)&As[k][ty * 8];
            *(float4*)&a[4] = *(const float4*)&As[k][ty * 8 + 4];
            float b[TN];
            *(float4*)&b[0] = *(const float4*)&Bs[k][tx * 4];
            if constexpr (BN == 128)
                *(float4*)&b[4] = *(const float4*)&Bs[k][64 + tx * 4];

            unsigned long long a2[4];
            #pragma unroll
            for (int p = 0; p < 4; p++) a2[p] = pack2(a[2 * p], a[2 * p + 1]);
            unsigned long long b2[TN];
            #pragma unroll
            for (int j = 0; j < TN; j++) b2[j] = pack2(b[j], b[j]);

            #pragma unroll
            for (int p = 0; p < 4; p++)
                #pragma unroll
                for (int j = 0; j < TN; j++)
                    ffma2(acc2[p][j], a2[p], b2[j]);
        }
        __syncthreads();
    }

    #pragma unroll
    for (int p = 0; p < 4; p++) {
        int r0 = row0 + ty * 8 + 2 * p;
        if (r0 >= M) continue;
        float s0 = 1.f, s1 = 1.f;
        if constexpr (SCALE_DINV) {
            s0 = g_dinv[r0];
            s1 = (r0 + 1 < M) ? g_dinv[r0 + 1] : 0.f;
        }
        float v0[TN], v1[TN];
        #pragma unroll
        for (int j = 0; j < TN; j++) {
            float lo, hi;
            unpack2(acc2[p][j], lo, hi);
            v0[j] = lo * s0; v1[j] = hi * s1;
        }
        *(float4*)&C[(size_t)r0 * BN + tx * 4] = *(float4*)&v0[0];
        if (r0 + 1 < M)
            *(float4*)&C[(size_t)(r0 + 1) * BN + tx * 4] = *(float4*)&v1[0];
        if constexpr (BN == 128) {
            *(float4*)&C[(size_t)r0 * BN + 64 + tx * 4] = *(float4*)&v0[4];
            if (r0 + 1 < M)
                *(float4*)&C[(size_t)(r0 + 1) * BN + 64 + tx * 4] = *(float4*)&v1[4];
        }
    }
}

__global__ void gemm1_kernel(const float* __restrict__ x, const float* __restrict__ W1) {
    sgemm_body<HID_DIM, false>(x, W1, g_xw, N_NODES);   // unscaled: no dinv dep
}
__global__ void gemm2_kernel(const float* __restrict__ W2) {
    sgemm_body<OUT_DIM, true>(g_h, W2, g_hw, N_NODES);
}

// ---------------- gather layer 1: warp per node, 8x unrolled, per-edge dinv ----
// h[d] = relu( dinv[d] * ( sum_s xw[s]*dinv[s] + xw[d]*dinv[d] ) + b1 )
__global__ void gather1_kernel(const float* __restrict__ b1) {
    int w = (blockIdx.x * blockDim.x + threadIdx.x) >> 5;
    int lane = threadIdx.x & 31;
    if (w >= N_NODES) return;
    int beg = g_rowstart[w];
    int end = g_rowstart[w + 1];
    const float4* xw4 = reinterpret_cast<const float4*>(g_xw);

    float dself = g_dinv[w];
    float4 self = xw4[(size_t)w * 32 + lane];
    float4 acc;
    acc.x = self.x * dself; acc.y = self.y * dself;
    acc.z = self.z * dself; acc.w = self.w * dself;

    int e = beg;
    for (; e + 7 < end; e += 8) {
        int sI[8]; float dv[8]; float4 v[8];
        #pragma unroll
        for (int i = 0; i < 8; i++) sI[i] = __ldg(&g_csr[e + i]);
        #pragma unroll
        for (int i = 0; i < 8; i++) dv[i] = __ldg(&g_dinv[sI[i]]);
        #pragma unroll
        for (int i = 0; i < 8; i++) v[i] = __ldg(&xw4[(size_t)sI[i] * 32 + lane]);
        #pragma unroll
        for (int i = 0; i < 8; i++) {
            acc.x = fmaf(v[i].x, dv[i], acc.x);
            acc.y = fmaf(v[i].y, dv[i], acc.y);
            acc.z = fmaf(v[i].z, dv[i], acc.z);
            acc.w = fmaf(v[i].w, dv[i], acc.w);
        }
    }
    for (; e < end; e++) {
        int s0 = __ldg(&g_csr[e]);
        float d0 = __ldg(&g_dinv[s0]);
        float4 v0 = __ldg(&xw4[(size_t)s0 * 32 + lane]);
        acc.x = fmaf(v0.x, d0, acc.x); acc.y = fmaf(v0.y, d0, acc.y);
        acc.z = fmaf(v0.z, d0, acc.z); acc.w = fmaf(v0.w, d0, acc.w);
    }
    float4 bb = reinterpret_cast<const float4*>(b1)[lane];
    float4 r;
    r.x = fmaxf(fmaf(dself, acc.x, bb.x), 0.f);
    r.y = fmaxf(fmaf(dself, acc.y, bb.y), 0.f);
    r.z = fmaxf(fmaf(dself, acc.z, bb.z), 0.f);
    r.w = fmaxf(fmaf(dself, acc.w, bb.w), 0.f);
    reinterpret_cast<float4*>(g_h)[(size_t)w * 32 + lane] = r;
}

// ---------------- gather layer 2 + FC + leaky, fully fused, 8x unrolled --------
__global__ void gather2_kernel(const float* __restrict__ b2,
                               const float* __restrict__ Wfc,
                               const float* __restrict__ bfc,
                               float* __restrict__ out) {
    int w = (blockIdx.x * blockDim.x + threadIdx.x) >> 5;
    int lane = threadIdx.x & 31;
    if (w >= N_NODES) return;
    int beg = g_rowstart[w];
    int end = g_rowstart[w + 1];
    const float2* hw2 = reinterpret_cast<const float2*>(g_hw);   // 32 float2/row

    float2 acc = hw2[(size_t)w * 32 + lane];    // self term (hw' already scaled)
    int e = beg;
    for (; e + 7 < end; e += 8) {
        int sI[8]; float2 v[8];
        #pragma unroll
        for (int i = 0; i < 8; i++) sI[i] = __ldg(&g_csr[e + i]);
        #pragma unroll
        for (int i = 0; i < 8; i++) v[i] = __ldg(&hw2[(size_t)sI[i] * 32 + lane]);
        #pragma unroll
        for (int i = 0; i < 8; i++) { acc.x += v[i].x; acc.y += v[i].y; }
    }
    for (; e < end; e++) {
        int s0 = __ldg(&g_csr[e]);
        float2 v0 = __ldg(&hw2[(size_t)s0 * 32 + lane]);
        acc.x += v0.x; acc.y += v0.y;
    }
    float di = g_dinv[w];
    float2 b2v = reinterpret_cast<const float2*>(b2)[lane];
    float vx = di * acc.x + b2v.x;              // feature 2*lane
    float vy = di * acc.y + b2v.y;              // feature 2*lane+1

    int f0 = 2 * lane, f1 = 2 * lane + 1;
    float p0 = vx * __ldg(&Wfc[f0 * 2 + 0]) + vy * __ldg(&Wfc[f1 * 2 + 0]);
    float p1 = vx * __ldg(&Wfc[f0 * 2 + 1]) + vy * __ldg(&Wfc[f1 * 2 + 1]);
    #pragma unroll
    for (int off = 16; off > 0; off >>= 1) {
        p0 += __shfl_xor_sync(0xffffffff, p0, off);
        p1 += __shfl_xor_sync(0xffffffff, p1, off);
    }
    if (lane == 0) {
        float o0 = p0 + __ldg(&bfc[0]);
        float o1 = p1 + __ldg(&bfc[1]);
        out[w * 2 + 0] = (o0 > 0.f) ? o0 : 0.01f * o0;
        out[w * 2 + 1] = (o1 > 0.f) ? o1 : 0.01f * o1;
    }
}

// ---------------- launch -------------------------------------------------------
// Fork-join: gemm1 (stream 0) overlaps the degree/CSR chain (side stream).
// Sequencing identical to R9 (the R10 gather/gemm2 pipelining regressed).
extern "C" void kernel_launch(void* const* d_in, const int* in_sizes, int n_in,
                              void* d_out, int out_size) {
    const float* x   = (const float*)d_in[0];
    const int*   ei  = (const int*)d_in[1];   // JAX default: int64 demoted to int32
    const float* W1  = (const float*)d_in[2];
    const float* b1  = (const float*)d_in[3];
    const float* W2  = (const float*)d_in[4];
    const float* b2  = (const float*)d_in[5];
    const float* Wfc = (const float*)d_in[6];
    const float* bfc = (const float*)d_in[7];
    float* out = (float*)d_out;

    const int* src = ei;
    const int* dst = ei + N_EDGES;

    static cudaStream_t s_side = nullptr;
    static cudaEvent_t  e_fork = nullptr, e_join = nullptr;
    if (s_side == nullptr) {
        cudaStreamCreateWithFlags(&s_side, cudaStreamNonBlocking);
        cudaEventCreateWithFlags(&e_fork, cudaEventDisableTiming);
        cudaEventCreateWithFlags(&e_join, cudaEventDisableTiming);
    }

    // fork side stream off the (captured) default stream
    cudaEventRecord(e_fork, 0);
    cudaStreamWaitEvent(s_side, e_fork, 0);

    // side stream: degree(+rank) + dinv + scan + atomic-free fill
    zero_kernel<<<(N_NODES + 255) / 256, 256, 0, s_side>>>();
    deg_kernel<<<(N_EDGES + 255) / 256, 256, 0, s_side>>>(dst);
    scan_kernel<<<SCAN_NB, SCAN_BS, 0, s_side>>>();   // single-pass + dinv
    fill_kernel<<<(N_EDGES / 4 + 255) / 256, 256, 0, s_side>>>(src, dst);
    cudaEventRecord(e_join, s_side);

    // default stream: gemm1 (independent of degree chain), then join
    gemm1_kernel<<<dim3(1, (N_NODES + 127) / 128), 256>>>(x, W1);
    cudaStreamWaitEvent(0, e_join, 0);

    // layer 1 aggregation (needs CSR + dinv + xw)
    gather1_kernel<<<(N_NODES * 32 + 255) / 256, 256>>>(b1);

    // layer 2 fused with FC + leaky relu
    gemm2_kernel<<<dim3(1, (N_NODES + 127) / 128), 256>>>(W2);
    gather2_kernel<<<(N_NODES * 32 + 255) / 256, 256>>>(b2, Wfc, bfc, out);
}

// round 12
// speedup vs baseline: 1.5400x; 1.2806x over previous
#include <cuda_runtime.h>
#include <cuda_bf16.h>
#include <cstdint>

#define N_NODES 50000
#define N_EDGES 800000
#define IN_DIM  128
#define HID_DIM 128
#define OUT_DIM 64

#define SCAN_BS   512
#define SCAN_NB   ((N_NODES + SCAN_BS - 1) / SCAN_BS)   // 98

// ---------------- scratch (device globals: no allocation allowed) -------------
// Only referenced from DEVICE code (host-side use of __device__ symbols gives
// the host shadow address -> silent ATS writes to host RAM; R5 bug).
__device__ __align__(16) int                g_degi    [N_NODES];
__device__ __align__(16) float              g_dinv    [N_NODES];
__device__ __align__(16) int                g_rowstart[N_NODES + 1];
__device__ __align__(16) int                g_rank    [N_EDGES];   // edge rank within dst
__device__ __align__(16) int                g_csr     [N_EDGES];   // src per CSR slot
__device__ __align__(16) unsigned long long g_state   [SCAN_NB];   // lookback states
__device__ __align__(16) float              g_xw      [N_NODES * HID_DIM];  // x@W1 (unscaled)
__device__ __align__(16) float              g_c2      [HID_DIM * 2];        // W2 @ Wfc
__device__ __align__(16) float              g_cbias   [2];                  // b2@Wfc + bfc
__device__ __align__(16) float              g_z       [N_NODES * 2];        // (relu(.)@c2)*dinv

// ---------------- packed f32x2 helpers -----------------------------------------
__device__ __forceinline__ unsigned long long pack2(float lo, float hi) {
    unsigned long long r;
    asm("mov.b64 %0, {%1, %2};" : "=l"(r)
        : "r"(__float_as_uint(lo)), "r"(__float_as_uint(hi)));
    return r;
}
__device__ __forceinline__ void unpack2(unsigned long long v, float& lo, float& hi) {
    unsigned a, b;
    asm("mov.b64 {%0, %1}, %2;" : "=r"(a), "=r"(b) : "l"(v));
    lo = __uint_as_float(a); hi = __uint_as_float(b);
}
__device__ __forceinline__ void ffma2(unsigned long long& d,
                                      unsigned long long a, unsigned long long b) {
    asm("fma.rn.f32x2 %0, %1, %2, %0;" : "+l"(d) : "l"(a), "l"(b));
}

// ---------------- zero: degrees + lookback states ------------------------------
__global__ void zero_kernel() {
    int i = blockIdx.x * blockDim.x + threadIdx.x;
    if (i < N_NODES) g_degi[i] = 0;
    if (i < SCAN_NB) g_state[i] = 0ull;
}

// ---------------- degree + per-edge rank (1 edge/thread: max MLP) --------------
__global__ void deg_kernel(const int* __restrict__ dst) {
    int e = blockIdx.x * blockDim.x + threadIdx.x;
    if (e >= N_EDGES) return;
    unsigned d = (unsigned)dst[e];
    g_rank[e] = (d < N_NODES) ? atomicAdd(&g_degi[d], 1) : 0;
}

// ---------------- single-pass scan (decoupled lookback) + fused dinv -----------
// 98 blocks <= 148 SMs: all co-resident, spin-lookback is deadlock-free.
__global__ void scan_kernel() {
    __shared__ int sm[SCAN_BS];
    __shared__ int s_excl;
    int t = threadIdx.x, b = blockIdx.x;
    int i = b * SCAN_BS + t;
    int s = (i < N_NODES) ? g_degi[i] : 0;
    if (i < N_NODES) g_dinv[i] = rsqrtf((float)s + 1.0f);   // fused dinv
    sm[t] = s;
    __syncthreads();
    #pragma unroll
    for (int off = 1; off < SCAN_BS; off <<= 1) {
        int v = (t >= off) ? sm[t - off] : 0;
        __syncthreads();
        sm[t] += v;
        __syncthreads();
    }
    int total = sm[SCAN_BS - 1];

    if (t == 0) {
        if (b == 0) {
            atomicExch(&g_state[0], (2ull << 32) | (unsigned)total);
            s_excl = 0;
        } else {
            atomicExch(&g_state[b], (1ull << 32) | (unsigned)total);
            int excl = 0;
            int idx = b - 1;
            while (true) {
                unsigned long long st = atomicAdd(&g_state[idx], 0ull);  // atomic read
                unsigned flag = (unsigned)(st >> 32);
                if (flag == 0u) { __nanosleep(20); continue; }
                excl += (int)(unsigned)st;
                if (flag == 2u) break;
                idx--;
            }
            atomicExch(&g_state[b], (2ull << 32) | (unsigned)(excl + total));
            s_excl = excl;
        }
    }
    __syncthreads();
    if (i < N_NODES) g_rowstart[i] = sm[t] - s + s_excl;   // exclusive prefix
    if (i == 0) g_rowstart[N_NODES] = N_EDGES;
}

// ---------------- CSR fill: atomic-free (slot = rowstart[d] + rank[e]) ---------
__global__ void fill_kernel(const int* __restrict__ src, const int* __restrict__ dst) {
    int e4 = (blockIdx.x * blockDim.x + threadIdx.x) * 4;
    if (e4 + 3 < N_EDGES) {
        int4 d = *(const int4*)&dst[e4];
        int4 s = *(const int4*)&src[e4];
        int4 r = *(const int4*)&g_rank[e4];
        if ((unsigned)d.x < N_NODES && (unsigned)s.x < N_NODES)
            g_csr[g_rowstart[d.x] + r.x] = s.x;
        if ((unsigned)d.y < N_NODES && (unsigned)s.y < N_NODES)
            g_csr[g_rowstart[d.y] + r.y] = s.y;
        if ((unsigned)d.z < N_NODES && (unsigned)s.z < N_NODES)
            g_csr[g_rowstart[d.z] + r.z] = s.z;
        if ((unsigned)d.w < N_NODES && (unsigned)s.w < N_NODES)
            g_csr[g_rowstart[d.w] + r.w] = s.w;
    } else {
        for (int e = e4; e < N_EDGES; e++) {
            unsigned d = (unsigned)dst[e], s = (unsigned)src[e];
            if (d < N_NODES && s < N_NODES)
                g_csr[g_rowstart[d] + g_rank[e]] = (int)s;
        }
    }
}

// ---------------- precompute c2 = W2 @ Wfc, cbias = b2 @ Wfc + bfc -------------
__global__ void wfc_kernel(const float* __restrict__ W2, const float* __restrict__ b2,
                           const float* __restrict__ Wfc, const float* __restrict__ bfc) {
    int f = threadIdx.x;                 // 128 threads, one feature each
    float c0 = 0.f, c1 = 0.f;
    #pragma unroll 8
    for (int k = 0; k < OUT_DIM; k++) {
        float w = W2[f * OUT_DIM + k];
        c0 = fmaf(w, Wfc[k * 2 + 0], c0);
        c1 = fmaf(w, Wfc[k * 2 + 1], c1);
    }
    g_c2[f * 2 + 0] = c0;
    g_c2[f * 2 + 1] = c1;
    if (f < 2) {
        float acc = bfc[f];
        for (int k = 0; k < OUT_DIM; k++) acc = fmaf(b2[k], Wfc[k * 2 + f], acc);
        g_cbias[f] = acc;
    }
}

// ---------------- SGEMM: 128x128 tile, FFMA2 microkernel (layer 1 only) --------
__global__ void gemm1_kernel(const float* __restrict__ A, const float* __restrict__ B) {
    constexpr int BM = 128, BN = 128, BK = 16, KD = 128, TN = 8;
    const int M = N_NODES;
    __shared__ float As[BK][BM];                // transposed A tile
    __shared__ float Bs[BK][BN];

    const int tid = threadIdx.x;                // 256 threads
    const int tx = tid & 15;
    const int ty = tid >> 4;
    const int row0 = blockIdx.y * BM;

    unsigned long long acc2[4][TN] = {};        // [row-pair][col]

    for (int k0 = 0; k0 < KD; k0 += BK) {
        {
            int idx = tid * 8;
            int m = idx >> 4, kk = idx & 15;    // kk in {0, 8}
            int r = row0 + m;
            float4 f0 = make_float4(0.f, 0.f, 0.f, 0.f), f1 = f0;
            if (r < M) {
                f0 = *(const float4*)&A[(size_t)r * KD + k0 + kk];
                f1 = *(const float4*)&A[(size_t)r * KD + k0 + kk + 4];
            }
            As[kk + 0][m] = f0.x; As[kk + 1][m] = f0.y;
            As[kk + 2][m] = f0.z; As[kk + 3][m] = f0.w;
            As[kk + 4][m] = f1.x; As[kk + 5][m] = f1.y;
            As[kk + 6][m] = f1.z; As[kk + 7][m] = f1.w;
        }
        {
            int idx = tid * 8;
            int kb = idx >> 7, n = idx & 127;
            const float* bp = &B[(size_t)(k0 + kb) * BN + n];
            *(float4*)&Bs[kb][n]     = *(const float4*)bp;
            *(float4*)&Bs[kb][n + 4] = *(const float4*)(bp + 4);
        }
        __syncthreads();

        #pragma unroll
        for (int k = 0; k < BK; k++) {
            float a[8];
            *(float4*)&a[0] = *(const float4*)&As[k][ty * 8];
            *(float4*)&a[4] = *(const float4*)&As[k][ty * 8 + 4];
            float b[TN];
            *(float4*)&b[0] = *(const float4*)&Bs[k][tx * 4];
            *(float4*)&b[4] = *(const float4*)&Bs[k][64 + tx * 4];

            unsigned long long a2[4];
            #pragma unroll
            for (int p = 0; p < 4; p++) a2[p] = pack2(a[2 * p], a[2 * p + 1]);
            unsigned long long b2[TN];
            #pragma unroll
            for (int j = 0; j < TN; j++) b2[j] = pack2(b[j], b[j]);

            #pragma unroll
            for (int p = 0; p < 4; p++)
                #pragma unroll
                for (int j = 0; j < TN; j++)
                    ffma2(acc2[p][j], a2[p], b2[j]);
        }
        __syncthreads();
    }

    #pragma unroll
    for (int p = 0; p < 4; p++) {
        int r0 = row0 + ty * 8 + 2 * p;
        if (r0 >= M) continue;
        float v0[TN], v1[TN];
        #pragma unroll
        for (int j = 0; j < TN; j++) unpack2(acc2[p][j], v0[j], v1[j]);
        *(float4*)&g_xw[(size_t)r0 * BN + tx * 4]      = *(float4*)&v0[0];
        *(float4*)&g_xw[(size_t)r0 * BN + 64 + tx * 4] = *(float4*)&v0[4];
        if (r0 + 1 < M) {
            *(float4*)&g_xw[(size_t)(r0 + 1) * BN + tx * 4]      = *(float4*)&v1[0];
            *(float4*)&g_xw[(size_t)(r0 + 1) * BN + 64 + tx * 4] = *(float4*)&v1[4];
        }
    }
}

// ---------------- gather1 fused: aggregate + relu + (@W2Wfc) + dinv ------------
// h_row = relu( dinv_d*(sum_s xw[s]*dinv[s] + xw[d]*dinv[d]) + b1 )
// z'[d] = (h_row @ c2) * dinv_d          (g_h / gemm2 never materialized)
__global__ void gather1_kernel(const float* __restrict__ b1) {
    int w = (blockIdx.x * blockDim.x + threadIdx.x) >> 5;
    int lane = threadIdx.x & 31;
    if (w >= N_NODES) return;
    int beg = g_rowstart[w];
    int end = g_rowstart[w + 1];
    const float4* xw4 = reinterpret_cast<const float4*>(g_xw);

    float dself = g_dinv[w];
    float4 self = xw4[(size_t)w * 32 + lane];
    float4 acc;
    acc.x = self.x * dself; acc.y = self.y * dself;
    acc.z = self.z * dself; acc.w = self.w * dself;

    int e = beg;
    for (; e + 7 < end; e += 8) {
        int sI[8]; float dv[8]; float4 v[8];
        #pragma unroll
        for (int i = 0; i < 8; i++) sI[i] = __ldg(&g_csr[e + i]);
        #pragma unroll
        for (int i = 0; i < 8; i++) dv[i] = __ldg(&g_dinv[sI[i]]);
        #pragma unroll
        for (int i = 0; i < 8; i++) v[i] = __ldg(&xw4[(size_t)sI[i] * 32 + lane]);
        #pragma unroll
        for (int i = 0; i < 8; i++) {
            acc.x = fmaf(v[i].x, dv[i], acc.x);
            acc.y = fmaf(v[i].y, dv[i], acc.y);
            acc.z = fmaf(v[i].z, dv[i], acc.z);
            acc.w = fmaf(v[i].w, dv[i], acc.w);
        }
    }
    for (; e < end; e++) {
        int s0 = __ldg(&g_csr[e]);
        float d0 = __ldg(&g_dinv[s0]);
        float4 v0 = __ldg(&xw4[(size_t)s0 * 32 + lane]);
        acc.x = fmaf(v0.x, d0, acc.x); acc.y = fmaf(v0.y, d0, acc.y);
        acc.z = fmaf(v0.z, d0, acc.z); acc.w = fmaf(v0.w, d0, acc.w);
    }
    float4 bb = reinterpret_cast<const float4*>(b1)[lane];
    float4 r;
    r.x = fmaxf(fmaf(dself, acc.x, bb.x), 0.f);
    r.y = fmaxf(fmaf(dself, acc.y, bb.y), 0.f);
    r.z = fmaxf(fmaf(dself, acc.z, bb.z), 0.f);
    r.w = fmaxf(fmaf(dself, acc.w, bb.w), 0.f);

    // z = h_row @ c2 : lane covers features 4*lane..4*lane+3 -> c2[8*lane..+7]
    float4 ca = *(const float4*)&g_c2[8 * lane];       // (f0c0,f0c1,f1c0,f1c1)
    float4 cb = *(const float4*)&g_c2[8 * lane + 4];   // (f2c0,f2c1,f3c0,f3c1)
    float z0 = r.x * ca.x + r.y * ca.z + r.z * cb.x + r.w * cb.z;
    float z1 = r.x * ca.y + r.y * ca.w + r.z * cb.y + r.w * cb.w;
    #pragma unroll
    for (int off = 16; off > 0; off >>= 1) {
        z0 += __shfl_xor_sync(0xffffffff, z0, off);
        z1 += __shfl_xor_sync(0xffffffff, z1, off);
    }
    if (lane == 0)
        *(float2*)&g_z[w * 2] = make_float2(z0 * dself, z1 * dself);
}

// ---------------- gather2': tiny float2 aggregation + leaky --------------------
// out[d] = leaky( dinv_d * (sum_s z'[s] + z'[d]) + cbias )
__global__ void gather2_kernel(float* __restrict__ out) {
    int w = (blockIdx.x * blockDim.x + threadIdx.x) >> 5;
    int lane = threadIdx.x & 31;
    if (w >= N_NODES) return;
    int beg = g_rowstart[w];
    int end = g_rowstart[w + 1];

    float ax = 0.f, ay = 0.f;
    for (int e = beg + lane; e < end; e += 32) {
        int s = __ldg(&g_csr[e]);
        float2 v = *(const float2*)&g_z[s * 2];
        ax += v.x; ay += v.y;
    }
    #pragma unroll
    for (int off = 16; off > 0; off >>= 1) {
        ax += __shfl_xor_sync(0xffffffff, ax, off);
        ay += __shfl_xor_sync(0xffffffff, ay, off);
    }
    if (lane == 0) {
        float di = g_dinv[w];
        float2 zs = *(const float2*)&g_z[w * 2];
        float o0 = fmaf(di, ax + zs.x, g_cbias[0]);
        float o1 = fmaf(di, ay + zs.y, g_cbias[1]);
        out[w * 2 + 0] = (o0 > 0.f) ? o0 : 0.01f * o0;
        out[w * 2 + 1] = (o1 > 0.f) ? o1 : 0.01f * o1;
    }
}

// ---------------- launch -------------------------------------------------------
// Fork-join: gemm1 + wfc (stream 0) overlap the degree/CSR chain (side stream).
extern "C" void kernel_launch(void* const* d_in, const int* in_sizes, int n_in,
                              void* d_out, int out_size) {
    const float* x   = (const float*)d_in[0];
    const int*   ei  = (const int*)d_in[1];   // JAX default: int64 demoted to int32
    const float* W1  = (const float*)d_in[2];
    const float* b1  = (const float*)d_in[3];
    const float* W2  = (const float*)d_in[4];
    const float* b2  = (const float*)d_in[5];
    const float* Wfc = (const float*)d_in[6];
    const float* bfc = (const float*)d_in[7];
    float* out = (float*)d_out;

    const int* src = ei;
    const int* dst = ei + N_EDGES;

    static cudaStream_t s_side = nullptr;
    static cudaEvent_t  e_fork = nullptr, e_join = nullptr;
    if (s_side == nullptr) {
        cudaStreamCreateWithFlags(&s_side, cudaStreamNonBlocking);
        cudaEventCreateWithFlags(&e_fork, cudaEventDisableTiming);
        cudaEventCreateWithFlags(&e_join, cudaEventDisableTiming);
    }

    // fork side stream off the (captured) default stream
    cudaEventRecord(e_fork, 0);
    cudaStreamWaitEvent(s_side, e_fork, 0);

    // side stream: degree(+rank) + dinv + scan + atomic-free fill
    zero_kernel<<<(N_NODES + 255) / 256, 256, 0, s_side>>>();
    deg_kernel<<<(N_EDGES + 255) / 256, 256, 0, s_side>>>(dst);
    scan_kernel<<<SCAN_NB, SCAN_BS, 0, s_side>>>();   // single-pass + dinv
    fill_kernel<<<(N_EDGES / 4 + 255) / 256, 256, 0, s_side>>>(src, dst);
    cudaEventRecord(e_join, s_side);

    // default stream: wfc precompute + gemm1 (independent of degree chain)
    wfc_kernel<<<1, 128>>>(W2, b2, Wfc, bfc);
    gemm1_kernel<<<dim3(1, (N_NODES + 127) / 128), 256>>>(x, W1);
    cudaStreamWaitEvent(0, e_join, 0);

    // fused layer-1 aggregation + relu + (W2 Wfc) projection + dinv scale
    gather1_kernel<<<(N_NODES * 32 + 255) / 256, 256>>>(b1);

    // tiny layer-2 aggregation + FC bias + leaky relu
    gather2_kernel<<<(N_NODES * 32 + 255) / 256, 256>>>(out);
}

// round 13
// speedup vs baseline: 1.6897x; 1.0972x over previous
#include <cuda_runtime.h>
#include <cuda_fp16.h>
#include <cuda_bf16.h>
#include <cstdint>

#define N_NODES 50000
#define N_EDGES 800000
#define IN_DIM  128
#define HID_DIM 128
#define OUT_DIM 64

#define SCAN_BS   512
#define SCAN_NB   ((N_NODES + SCAN_BS - 1) / SCAN_BS)   // 98

// ---------------- scratch (device globals: no allocation allowed) -------------
// Only referenced from DEVICE code (host-side use of __device__ symbols gives
// the host shadow address -> silent ATS writes to host RAM; R5 bug).
__device__ __align__(16) int                g_degi    [N_NODES];
__device__ __align__(16) float              g_dinv    [N_NODES];
__device__ __align__(16) int                g_rowstart[N_NODES + 1];
__device__ __align__(16) int                g_rank    [N_EDGES];   // edge rank within dst
__device__ __align__(16) int                g_csr     [N_EDGES];   // src per CSR slot
__device__ __align__(16) unsigned long long g_state   [SCAN_NB];   // lookback states
__device__ __align__(16) __half             g_xwh     [N_NODES * HID_DIM];  // x@W1, fp16
__device__ __align__(16) float              g_c2      [HID_DIM * 2];        // W2 @ Wfc
__device__ __align__(16) float              g_cbias   [2];                  // b2@Wfc + bfc
__device__ __align__(16) float              g_z       [N_NODES * 2];        // (relu(.)@c2)*dinv

// ---------------- packed f32x2 helpers -----------------------------------------
__device__ __forceinline__ unsigned long long pack2(float lo, float hi) {
    unsigned long long r;
    asm("mov.b64 %0, {%1, %2};" : "=l"(r)
        : "r"(__float_as_uint(lo)), "r"(__float_as_uint(hi)));
    return r;
}
__device__ __forceinline__ void unpack2(unsigned long long v, float& lo, float& hi) {
    unsigned a, b;
    asm("mov.b64 {%0, %1}, %2;" : "=r"(a), "=r"(b) : "l"(v));
    lo = __uint_as_float(a); hi = __uint_as_float(b);
}
__device__ __forceinline__ void ffma2(unsigned long long& d,
                                      unsigned long long a, unsigned long long b) {
    asm("fma.rn.f32x2 %0, %1, %2, %0;" : "+l"(d) : "l"(a), "l"(b));
}

// load 4 halves (8B) and widen to float4
__device__ __forceinline__ float4 ldg_half4(const __half* p) {
    uint2 u = __ldg(reinterpret_cast<const uint2*>(p));
    __half2 h0 = *reinterpret_cast<__half2*>(&u.x);
    __half2 h1 = *reinterpret_cast<__half2*>(&u.y);
    float2 f0 = __half22float2(h0);
    float2 f1 = __half22float2(h1);
    return make_float4(f0.x, f0.y, f1.x, f1.y);
}

// ---------------- zero: degrees + lookback states ------------------------------
__global__ void zero_kernel() {
    int i = blockIdx.x * blockDim.x + threadIdx.x;
    if (i < N_NODES) g_degi[i] = 0;
    if (i < SCAN_NB) g_state[i] = 0ull;
}

// ---------------- degree + per-edge rank (1 edge/thread: max MLP) --------------
__global__ void deg_kernel(const int* __restrict__ dst) {
    int e = blockIdx.x * blockDim.x + threadIdx.x;
    if (e >= N_EDGES) return;
    unsigned d = (unsigned)dst[e];
    g_rank[e] = (d < N_NODES) ? atomicAdd(&g_degi[d], 1) : 0;
}

// ---------------- single-pass scan (decoupled lookback) + fused dinv -----------
// 98 blocks <= 148 SMs: all co-resident, spin-lookback is deadlock-free.
__global__ void scan_kernel() {
    __shared__ int sm[SCAN_BS];
    __shared__ int s_excl;
    int t = threadIdx.x, b = blockIdx.x;
    int i = b * SCAN_BS + t;
    int s = (i < N_NODES) ? g_degi[i] : 0;
    if (i < N_NODES) g_dinv[i] = rsqrtf((float)s + 1.0f);   // fused dinv
    sm[t] = s;
    __syncthreads();
    #pragma unroll
    for (int off = 1; off < SCAN_BS; off <<= 1) {
        int v = (t >= off) ? sm[t - off] : 0;
        __syncthreads();
        sm[t] += v;
        __syncthreads();
    }
    int total = sm[SCAN_BS - 1];

    if (t == 0) {
        if (b == 0) {
            atomicExch(&g_state[0], (2ull << 32) | (unsigned)total);
            s_excl = 0;
        } else {
            atomicExch(&g_state[b], (1ull << 32) | (unsigned)total);
            int excl = 0;
            int idx = b - 1;
            while (true) {
                unsigned long long st = atomicAdd(&g_state[idx], 0ull);  // atomic read
                unsigned flag = (unsigned)(st >> 32);
                if (flag == 0u) { __nanosleep(20); continue; }
                excl += (int)(unsigned)st;
                if (flag == 2u) break;
                idx--;
            }
            atomicExch(&g_state[b], (2ull << 32) | (unsigned)(excl + total));
            s_excl = excl;
        }
    }
    __syncthreads();
    if (i < N_NODES) g_rowstart[i] = sm[t] - s + s_excl;   // exclusive prefix
    if (i == 0) g_rowstart[N_NODES] = N_EDGES;
}

// ---------------- CSR fill: atomic-free (slot = rowstart[d] + rank[e]) ---------
__global__ void fill_kernel(const int* __restrict__ src, const int* __restrict__ dst) {
    int e4 = (blockIdx.x * blockDim.x + threadIdx.x) * 4;
    if (e4 + 3 < N_EDGES) {
        int4 d = *(const int4*)&dst[e4];
        int4 s = *(const int4*)&src[e4];
        int4 r = *(const int4*)&g_rank[e4];
        if ((unsigned)d.x < N_NODES && (unsigned)s.x < N_NODES)
            g_csr[g_rowstart[d.x] + r.x] = s.x;
        if ((unsigned)d.y < N_NODES && (unsigned)s.y < N_NODES)
            g_csr[g_rowstart[d.y] + r.y] = s.y;
        if ((unsigned)d.z < N_NODES && (unsigned)s.z < N_NODES)
            g_csr[g_rowstart[d.z] + r.z] = s.z;
        if ((unsigned)d.w < N_NODES && (unsigned)s.w < N_NODES)
            g_csr[g_rowstart[d.w] + r.w] = s.w;
    } else {
        for (int e = e4; e < N_EDGES; e++) {
            unsigned d = (unsigned)dst[e], s = (unsigned)src[e];
            if (d < N_NODES && s < N_NODES)
                g_csr[g_rowstart[d] + g_rank[e]] = (int)s;
        }
    }
}

// ---------------- precompute c2 = W2 @ Wfc, cbias = b2 @ Wfc + bfc -------------
__global__ void wfc_kernel(const float* __restrict__ W2, const float* __restrict__ b2,
                           const float* __restrict__ Wfc, const float* __restrict__ bfc) {
    int f = threadIdx.x;                 // 128 threads, one feature each
    float c0 = 0.f, c1 = 0.f;
    #pragma unroll 8
    for (int k = 0; k < OUT_DIM; k++) {
        float w = W2[f * OUT_DIM + k];
        c0 = fmaf(w, Wfc[k * 2 + 0], c0);
        c1 = fmaf(w, Wfc[k * 2 + 1], c1);
    }
    g_c2[f * 2 + 0] = c0;
    g_c2[f * 2 + 1] = c1;
    if (f < 2) {
        float acc = bfc[f];
        for (int k = 0; k < OUT_DIM; k++) acc = fmaf(b2[k], Wfc[k * 2 + f], acc);
        g_cbias[f] = acc;
    }
}

// ---------------- SGEMM: 128x128 tile, FFMA2 microkernel, fp16 epilogue --------
__global__ void gemm1_kernel(const float* __restrict__ A, const float* __restrict__ B) {
    constexpr int BM = 128, BN = 128, BK = 16, KD = 128, TN = 8;
    const int M = N_NODES;
    __shared__ float As[BK][BM];                // transposed A tile
    __shared__ float Bs[BK][BN];

    const int tid = threadIdx.x;                // 256 threads
    const int tx = tid & 15;
    const int ty = tid >> 4;
    const int row0 = blockIdx.y * BM;

    unsigned long long acc2[4][TN] = {};        // [row-pair][col]

    for (int k0 = 0; k0 < KD; k0 += BK) {
        {
            int idx = tid * 8;
            int m = idx >> 4, kk = idx & 15;    // kk in {0, 8}
            int r = row0 + m;
            float4 f0 = make_float4(0.f, 0.f, 0.f, 0.f), f1 = f0;
            if (r < M) {
                f0 = *(const float4*)&A[(size_t)r * KD + k0 + kk];
                f1 = *(const float4*)&A[(size_t)r * KD + k0 + kk + 4];
            }
            As[kk + 0][m] = f0.x; As[kk + 1][m] = f0.y;
            As[kk + 2][m] = f0.z; As[kk + 3][m] = f0.w;
            As[kk + 4][m] = f1.x; As[kk + 5][m] = f1.y;
            As[kk + 6][m] = f1.z; As[kk + 7][m] = f1.w;
        }
        {
            int idx = tid * 8;
            int kb = idx >> 7, n = idx & 127;
            const float* bp = &B[(size_t)(k0 + kb) * BN + n];
            *(float4*)&Bs[kb][n]     = *(const float4*)bp;
            *(float4*)&Bs[kb][n + 4] = *(const float4*)(bp + 4);
        }
        __syncthreads();

        #pragma unroll
        for (int k = 0; k < BK; k++) {
            float a[8];
            *(float4*)&a[0] = *(const float4*)&As[k][ty * 8];
            *(float4*)&a[4] = *(const float4*)&As[k][ty * 8 + 4];
            float b[TN];
            *(float4*)&b[0] = *(const float4*)&Bs[k][tx * 4];
            *(float4*)&b[4] = *(const float4*)&Bs[k][64 + tx * 4];

            unsigned long long a2[4];
            #pragma unroll
            for (int p = 0; p < 4; p++) a2[p] = pack2(a[2 * p], a[2 * p + 1]);
            unsigned long long b2[TN];
            #pragma unroll
            for (int j = 0; j < TN; j++) b2[j] = pack2(b[j], b[j]);

            #pragma unroll
            for (int p = 0; p < 4; p++)
                #pragma unroll
                for (int j = 0; j < TN; j++)
                    ffma2(acc2[p][j], a2[p], b2[j]);
        }
        __syncthreads();
    }

    #pragma unroll
    for (int p = 0; p < 4; p++) {
        int r0 = row0 + ty * 8 + 2 * p;
        if (r0 >= M) continue;
        float v0[TN], v1[TN];
        #pragma unroll
        for (int j = 0; j < TN; j++) unpack2(acc2[p][j], v0[j], v1[j]);
        // fp16 stores: 4 halves (8B) per column group
        {
            __half2 a0 = __float22half2_rn(make_float2(v0[0], v0[1]));
            __half2 a1 = __float22half2_rn(make_float2(v0[2], v0[3]));
            __half2 b0 = __float22half2_rn(make_float2(v0[4], v0[5]));
            __half2 b1 = __float22half2_rn(make_float2(v0[6], v0[7]));
            uint2 ua = make_uint2(*(unsigned*)&a0, *(unsigned*)&a1);
            uint2 ub = make_uint2(*(unsigned*)&b0, *(unsigned*)&b1);
            *(uint2*)&g_xwh[(size_t)r0 * BN + tx * 4]      = ua;
            *(uint2*)&g_xwh[(size_t)r0 * BN + 64 + tx * 4] = ub;
        }
        if (r0 + 1 < M) {
            __half2 a0 = __float22half2_rn(make_float2(v1[0], v1[1]));
            __half2 a1 = __float22half2_rn(make_float2(v1[2], v1[3]));
            __half2 b0 = __float22half2_rn(make_float2(v1[4], v1[5]));
            __half2 b1 = __float22half2_rn(make_float2(v1[6], v1[7]));
            uint2 ua = make_uint2(*(unsigned*)&a0, *(unsigned*)&a1);
            uint2 ub = make_uint2(*(unsigned*)&b0, *(unsigned*)&b1);
            *(uint2*)&g_xwh[(size_t)(r0 + 1) * BN + tx * 4]      = ua;
            *(uint2*)&g_xwh[(size_t)(r0 + 1) * BN + 64 + tx * 4] = ub;
        }
    }
}

// ---------------- gather1 fused: aggregate + relu + (@W2Wfc) + dinv ------------
// h_row = relu( dinv_d*(sum_s xw[s]*dinv[s] + xw[d]*dinv[d]) + b1 )
// z'[d] = (h_row @ c2) * dinv_d          (fp16 xw rows; fp32 accumulation)
__global__ void gather1_kernel(const float* __restrict__ b1) {
    int w = (blockIdx.x * blockDim.x + threadIdx.x) >> 5;
    int lane = threadIdx.x & 31;
    if (w >= N_NODES) return;
    int beg = g_rowstart[w];
    int end = g_rowstart[w + 1];
    const int fo = 4 * lane;                    // this lane's feature offset

    float dself = g_dinv[w];
    float4 self = ldg_half4(&g_xwh[(size_t)w * HID_DIM + fo]);
    float4 acc;
    acc.x = self.x * dself; acc.y = self.y * dself;
    acc.z = self.z * dself; acc.w = self.w * dself;

    int e = beg;
    for (; e + 7 < end; e += 8) {
        int sI[8]; float dv[8]; float4 v[8];
        #pragma unroll
        for (int i = 0; i < 8; i++) sI[i] = __ldg(&g_csr[e + i]);
        #pragma unroll
        for (int i = 0; i < 8; i++) dv[i] = __ldg(&g_dinv[sI[i]]);
        #pragma unroll
        for (int i = 0; i < 8; i++) v[i] = ldg_half4(&g_xwh[(size_t)sI[i] * HID_DIM + fo]);
        #pragma unroll
        for (int i = 0; i < 8; i++) {
            acc.x = fmaf(v[i].x, dv[i], acc.x);
            acc.y = fmaf(v[i].y, dv[i], acc.y);
            acc.z = fmaf(v[i].z, dv[i], acc.z);
            acc.w = fmaf(v[i].w, dv[i], acc.w);
        }
    }
    for (; e < end; e++) {
        int s0 = __ldg(&g_csr[e]);
        float d0 = __ldg(&g_dinv[s0]);
        float4 v0 = ldg_half4(&g_xwh[(size_t)s0 * HID_DIM + fo]);
        acc.x = fmaf(v0.x, d0, acc.x); acc.y = fmaf(v0.y, d0, acc.y);
        acc.z = fmaf(v0.z, d0, acc.z); acc.w = fmaf(v0.w, d0, acc.w);
    }
    float4 bb = reinterpret_cast<const float4*>(b1)[lane];
    float4 r;
    r.x = fmaxf(fmaf(dself, acc.x, bb.x), 0.f);
    r.y = fmaxf(fmaf(dself, acc.y, bb.y), 0.f);
    r.z = fmaxf(fmaf(dself, acc.z, bb.z), 0.f);
    r.w = fmaxf(fmaf(dself, acc.w, bb.w), 0.f);

    // z = h_row @ c2 : lane covers features 4*lane..4*lane+3 -> c2[8*lane..+7]
    float4 ca = *(const float4*)&g_c2[8 * lane];       // (f0c0,f0c1,f1c0,f1c1)
    float4 cb = *(const float4*)&g_c2[8 * lane + 4];   // (f2c0,f2c1,f3c0,f3c1)
    float z0 = r.x * ca.x + r.y * ca.z + r.z * cb.x + r.w * cb.z;
    float z1 = r.x * ca.y + r.y * ca.w + r.z * cb.y + r.w * cb.w;
    #pragma unroll
    for (int off = 16; off > 0; off >>= 1) {
        z0 += __shfl_xor_sync(0xffffffff, z0, off);
        z1 += __shfl_xor_sync(0xffffffff, z1, off);
    }
    if (lane == 0)
        *(float2*)&g_z[w * 2] = make_float2(z0 * dself, z1 * dself);
}

// ---------------- gather2': tiny float2 aggregation + leaky --------------------
// out[d] = leaky( dinv_d * (sum_s z'[s] + z'[d]) + cbias )
__global__ void gather2_kernel(float* __restrict__ out) {
    int w = (blockIdx.x * blockDim.x + threadIdx.x) >> 5;
    int lane = threadIdx.x & 31;
    if (w >= N_NODES) return;
    int beg = g_rowstart[w];
    int end = g_rowstart[w + 1];

    float ax = 0.f, ay = 0.f;
    for (int e = beg + lane; e < end; e += 32) {
        int s = __ldg(&g_csr[e]);
        float2 v = *(const float2*)&g_z[s * 2];
        ax += v.x; ay += v.y;
    }
    #pragma unroll
    for (int off = 16; off > 0; off >>= 1) {
        ax += __shfl_xor_sync(0xffffffff, ax, off);
        ay += __shfl_xor_sync(0xffffffff, ay, off);
    }
    if (lane == 0) {
        float di = g_dinv[w];
        float2 zs = *(const float2*)&g_z[w * 2];
        float o0 = fmaf(di, ax + zs.x, g_cbias[0]);
        float o1 = fmaf(di, ay + zs.y, g_cbias[1]);
        out[w * 2 + 0] = (o0 > 0.f) ? o0 : 0.01f * o0;
        out[w * 2 + 1] = (o1 > 0.f) ? o1 : 0.01f * o1;
    }
}

// ---------------- launch -------------------------------------------------------
// Fork-join: gemm1 + wfc (stream 0) overlap the degree/CSR chain (side stream).
extern "C" void kernel_launch(void* const* d_in, const int* in_sizes, int n_in,
                              void* d_out, int out_size) {
    const float* x   = (const float*)d_in[0];
    const int*   ei  = (const int*)d_in[1];   // JAX default: int64 demoted to int32
    const float* W1  = (const float*)d_in[2];
    const float* b1  = (const float*)d_in[3];
    const float* W2  = (const float*)d_in[4];
    const float* b2  = (const float*)d_in[5];
    const float* Wfc = (const float*)d_in[6];
    const float* bfc = (const float*)d_in[7];
    float* out = (float*)d_out;

    const int* src = ei;
    const int* dst = ei + N_EDGES;

    static cudaStream_t s_side = nullptr;
    static cudaEvent_t  e_fork = nullptr, e_join = nullptr;
    if (s_side == nullptr) {
        cudaStreamCreateWithFlags(&s_side, cudaStreamNonBlocking);
        cudaEventCreateWithFlags(&e_fork, cudaEventDisableTiming);
        cudaEventCreateWithFlags(&e_join, cudaEventDisableTiming);
    }

    // fork side stream off the (captured) default stream
    cudaEventRecord(e_fork, 0);
    cudaStreamWaitEvent(s_side, e_fork, 0);

    // side stream: degree(+rank) + dinv + scan + atomic-free fill
    zero_kernel<<<(N_NODES + 255) / 256, 256, 0, s_side>>>();
    deg_kernel<<<(N_EDGES + 255) / 256, 256, 0, s_side>>>(dst);
    scan_kernel<<<SCAN_NB, SCAN_BS, 0, s_side>>>();   // single-pass + dinv
    fill_kernel<<<(N_EDGES / 4 + 255) / 256, 256, 0, s_side>>>(src, dst);
    cudaEventRecord(e_join, s_side);

    // default stream: wfc precompute + gemm1 (independent of degree chain)
    wfc_kernel<<<1, 128>>>(W2, b2, Wfc, bfc);
    gemm1_kernel<<<dim3(1, (N_NODES + 127) / 128), 256>>>(x, W1);
    cudaStreamWaitEvent(0, e_join, 0);

    // fused layer-1 aggregation + relu + (W2 Wfc) projection + dinv scale
    gather1_kernel<<<(N_NODES * 32 + 255) / 256, 256>>>(b1);

    // tiny layer-2 aggregation + FC bias + leaky relu
    gather2_kernel<<<(N_NODES * 32 + 255) / 256, 256>>>(out);
}

// round 14
// speedup vs baseline: 1.7694x; 1.0472x over previous
#include <cuda_runtime.h>
#include <cuda_fp16.h>
#include <cuda_bf16.h>
#include <cstdint>

#define N_NODES 50000
#define N_EDGES 800000
#define IN_DIM  128
#define HID_DIM 128
#define OUT_DIM 64

#define SCAN_BS   512
#define SCAN_NB   ((N_NODES + SCAN_BS - 1) / SCAN_BS)   // 98

// ---------------- scratch (device globals: no allocation allowed) -------------
// Only referenced from DEVICE code (host-side use of __device__ symbols gives
// the host shadow address -> silent ATS writes to host RAM; R5 bug).
// Zero-at-end-of-use protocol (no zero_kernel):
//   g_degi : zeroed at load; scan_kernel re-zeroes after reading -> ready for
//            next call's deg_kernel. Every call runs the same sequence.
//   g_state: zeroed at load; deg_kernel re-zeroes (before scan uses it).
__device__ __align__(16) int                g_degi    [N_NODES];
__device__ __align__(16) float              g_dinv    [N_NODES];
__device__ __align__(16) int                g_rowstart[N_NODES + 1];
__device__ __align__(16) int                g_rank    [N_EDGES];   // edge rank within dst
__device__ __align__(16) int                g_csr     [N_EDGES];   // src per CSR slot
__device__ __align__(16) unsigned long long g_state   [SCAN_NB];   // lookback states
__device__ __align__(16) __half             g_xwh     [N_NODES * HID_DIM];  // x@W1, fp16
__device__ __align__(16) float              g_c2      [HID_DIM * 2];        // W2 @ Wfc
__device__ __align__(16) float              g_cbias   [2];                  // b2@Wfc + bfc
__device__ __align__(16) float              g_z       [N_NODES * 2];        // (relu(.)@c2)*dinv

// ---------------- packed f32x2 helpers -----------------------------------------
__device__ __forceinline__ unsigned long long pack2(float lo, float hi) {
    unsigned long long r;
    asm("mov.b64 %0, {%1, %2};" : "=l"(r)
        : "r"(__float_as_uint(lo)), "r"(__float_as_uint(hi)));
    return r;
}
__device__ __forceinline__ void unpack2(unsigned long long v, float& lo, float& hi) {
    unsigned a, b;
    asm("mov.b64 {%0, %1}, %2;" : "=r"(a), "=r"(b) : "l"(v));
    lo = __uint_as_float(a); hi = __uint_as_float(b);
}
__device__ __forceinline__ void ffma2(unsigned long long& d,
                                      unsigned long long a, unsigned long long b) {
    asm("fma.rn.f32x2 %0, %1, %2, %0;" : "+l"(d) : "l"(a), "l"(b));
}

// load 4 halves (8B) and widen to float4
__device__ __forceinline__ float4 ldg_half4(const __half* p) {
    uint2 u = __ldg(reinterpret_cast<const uint2*>(p));
    __half2 h0 = *reinterpret_cast<__half2*>(&u.x);
    __half2 h1 = *reinterpret_cast<__half2*>(&u.y);
    float2 f0 = __half22float2(h0);
    float2 f1 = __half22float2(h1);
    return make_float4(f0.x, f0.y, f1.x, f1.y);
}

// ---------------- degree + per-edge rank; also re-zero g_state -----------------
__global__ void deg_kernel(const int* __restrict__ dst) {
    int e = blockIdx.x * blockDim.x + threadIdx.x;
    if (e < SCAN_NB) g_state[e] = 0ull;      // reset lookback states for scan
    if (e >= N_EDGES) return;
    unsigned d = (unsigned)dst[e];
    g_rank[e] = (d < N_NODES) ? atomicAdd(&g_degi[d], 1) : 0;
}

// ---------------- single-pass scan (decoupled lookback, shfl-based) ------------
// 98 blocks <= 148 SMs: all co-resident, spin-lookback is deadlock-free.
// Also: fused dinv, and re-zeroes g_degi for the next call.
__global__ void scan_kernel() {
    __shared__ int warp_tot[16];
    __shared__ int s_excl;
    int t = threadIdx.x, b = blockIdx.x;
    int lane = t & 31, wid = t >> 5;
    int i = b * SCAN_BS + t;
    int s = (i < N_NODES) ? g_degi[i] : 0;
    if (i < N_NODES) {
        g_dinv[i] = rsqrtf((float)s + 1.0f);   // fused dinv
        g_degi[i] = 0;                          // re-zero for next call
    }

    // warp inclusive scan
    int v = s;
    #pragma unroll
    for (int off = 1; off < 32; off <<= 1) {
        int n = __shfl_up_sync(0xffffffff, v, off);
        if (lane >= off) v += n;
    }
    if (lane == 31) warp_tot[wid] = v;
    __syncthreads();
    if (wid == 0) {
        int wv = (lane < 16) ? warp_tot[lane] : 0;
        #pragma unroll
        for (int off = 1; off < 16; off <<= 1) {
            int n = __shfl_up_sync(0xffffffff, wv, off);
            if (lane >= off) wv += n;
        }
        if (lane < 16) warp_tot[lane] = wv;     // inclusive warp totals
    }
    __syncthreads();
    int incl = v + ((wid > 0) ? warp_tot[wid - 1] : 0);   // block-inclusive
    int total = warp_tot[15];

    if (t == 0) {
        if (b == 0) {
            atomicExch(&g_state[0], (2ull << 32) | (unsigned)total);
            s_excl = 0;
        } else {
            atomicExch(&g_state[b], (1ull << 32) | (unsigned)total);
            int excl = 0;
            int idx = b - 1;
            while (true) {
                unsigned long long st = atomicAdd(&g_state[idx], 0ull);  // atomic read
                unsigned flag = (unsigned)(st >> 32);
                if (flag == 0u) { __nanosleep(20); continue; }
                excl += (int)(unsigned)st;
                if (flag == 2u) break;
                idx--;
            }
            atomicExch(&g_state[b], (2ull << 32) | (unsigned)(excl + total));
            s_excl = excl;
        }
    }
    __syncthreads();
    if (i < N_NODES) g_rowstart[i] = incl - s + s_excl;   // exclusive prefix
    if (i == 0) g_rowstart[N_NODES] = N_EDGES;
}

// ---------------- CSR fill: atomic-free (slot = rowstart[d] + rank[e]) ---------
__global__ void fill_kernel(const int* __restrict__ src, const int* __restrict__ dst) {
    int e4 = (blockIdx.x * blockDim.x + threadIdx.x) * 4;
    if (e4 + 3 < N_EDGES) {
        int4 d = *(const int4*)&dst[e4];
        int4 s = *(const int4*)&src[e4];
        int4 r = *(const int4*)&g_rank[e4];
        if ((unsigned)d.x < N_NODES && (unsigned)s.x < N_NODES)
            g_csr[g_rowstart[d.x] + r.x] = s.x;
        if ((unsigned)d.y < N_NODES && (unsigned)s.y < N_NODES)
            g_csr[g_rowstart[d.y] + r.y] = s.y;
        if ((unsigned)d.z < N_NODES && (unsigned)s.z < N_NODES)
            g_csr[g_rowstart[d.z] + r.z] = s.z;
        if ((unsigned)d.w < N_NODES && (unsigned)s.w < N_NODES)
            g_csr[g_rowstart[d.w] + r.w] = s.w;
    } else {
        for (int e = e4; e < N_EDGES; e++) {
            unsigned d = (unsigned)dst[e], s = (unsigned)src[e];
            if (d < N_NODES && s < N_NODES)
                g_csr[g_rowstart[d] + g_rank[e]] = (int)s;
        }
    }
}

// ---------------- precompute c2 = W2 @ Wfc, cbias = b2 @ Wfc + bfc -------------
__global__ void wfc_kernel(const float* __restrict__ W2, const float* __restrict__ b2,
                           const float* __restrict__ Wfc, const float* __restrict__ bfc) {
    int f = threadIdx.x;                 // 128 threads, one feature each
    float c0 = 0.f, c1 = 0.f;
    #pragma unroll 8
    for (int k = 0; k < OUT_DIM; k++) {
        float w = W2[f * OUT_DIM + k];
        c0 = fmaf(w, Wfc[k * 2 + 0], c0);
        c1 = fmaf(w, Wfc[k * 2 + 1], c1);
    }
    g_c2[f * 2 + 0] = c0;
    g_c2[f * 2 + 1] = c1;
    if (f < 2) {
        float acc = bfc[f];
        for (int k = 0; k < OUT_DIM; k++) acc = fmaf(b2[k], Wfc[k * 2 + f], acc);
        g_cbias[f] = acc;
    }
}

// ---------------- SGEMM: 128x128 tile, FFMA2 microkernel, fp16 epilogue --------
__global__ void gemm1_kernel(const float* __restrict__ A, const float* __restrict__ B) {
    constexpr int BM = 128, BN = 128, BK = 16, KD = 128, TN = 8;
    const int M = N_NODES;
    __shared__ float As[BK][BM];                // transposed A tile
    __shared__ float Bs[BK][BN];

    const int tid = threadIdx.x;                // 256 threads
    const int tx = tid & 15;
    const int ty = tid >> 4;
    const int row0 = blockIdx.y * BM;

    unsigned long long acc2[4][TN] = {};        // [row-pair][col]

    for (int k0 = 0; k0 < KD; k0 += BK) {
        {
            int idx = tid * 8;
            int m = idx >> 4, kk = idx & 15;    // kk in {0, 8}
            int r = row0 + m;
            float4 f0 = make_float4(0.f, 0.f, 0.f, 0.f), f1 = f0;
            if (r < M) {
                f0 = *(const float4*)&A[(size_t)r * KD + k0 + kk];
                f1 = *(const float4*)&A[(size_t)r * KD + k0 + kk + 4];
            }
            As[kk + 0][m] = f0.x; As[kk + 1][m] = f0.y;
            As[kk + 2][m] = f0.z; As[kk + 3][m] = f0.w;
            As[kk + 4][m] = f1.x; As[kk + 5][m] = f1.y;
            As[kk + 6][m] = f1.z; As[kk + 7][m] = f1.w;
        }
        {
            int idx = tid * 8;
            int kb = idx >> 7, n = idx & 127;
            const float* bp = &B[(size_t)(k0 + kb) * BN + n];
            *(float4*)&Bs[kb][n]     = *(const float4*)bp;
            *(float4*)&Bs[kb][n + 4] = *(const float4*)(bp + 4);
        }
        __syncthreads();

        #pragma unroll
        for (int k = 0; k < BK; k++) {
            float a[8];
            *(float4*)&a[0] = *(const float4*)&As[k][ty * 8];
            *(float4*)&a[4] = *(const float4*)&As[k][ty * 8 + 4];
            float b[TN];
            *(float4*)&b[0] = *(const float4*)&Bs[k][tx * 4];
            *(float4*)&b[4] = *(const float4*)&Bs[k][64 + tx * 4];

            unsigned long long a2[4];
            #pragma unroll
            for (int p = 0; p < 4; p++) a2[p] = pack2(a[2 * p], a[2 * p + 1]);
            unsigned long long b2[TN];
            #pragma unroll
            for (int j = 0; j < TN; j++) b2[j] = pack2(b[j], b[j]);

            #pragma unroll
            for (int p = 0; p < 4; p++)
                #pragma unroll
                for (int j = 0; j < TN; j++)
                    ffma2(acc2[p][j], a2[p], b2[j]);
        }
        __syncthreads();
    }

    #pragma unroll
    for (int p = 0; p < 4; p++) {
        int r0 = row0 + ty * 8 + 2 * p;
        if (r0 >= M) continue;
        float v0[TN], v1[TN];
        #pragma unroll
        for (int j = 0; j < TN; j++) unpack2(acc2[p][j], v0[j], v1[j]);
        {
            __half2 a0 = __float22half2_rn(make_float2(v0[0], v0[1]));
            __half2 a1 = __float22half2_rn(make_float2(v0[2], v0[3]));
            __half2 b0 = __float22half2_rn(make_float2(v0[4], v0[5]));
            __half2 b1 = __float22half2_rn(make_float2(v0[6], v0[7]));
            uint2 ua = make_uint2(*(unsigned*)&a0, *(unsigned*)&a1);
            uint2 ub = make_uint2(*(unsigned*)&b0, *(unsigned*)&b1);
            *(uint2*)&g_xwh[(size_t)r0 * BN + tx * 4]      = ua;
            *(uint2*)&g_xwh[(size_t)r0 * BN + 64 + tx * 4] = ub;
        }
        if (r0 + 1 < M) {
            __half2 a0 = __float22half2_rn(make_float2(v1[0], v1[1]));
            __half2 a1 = __float22half2_rn(make_float2(v1[2], v1[3]));
            __half2 b0 = __float22half2_rn(make_float2(v1[4], v1[5]));
            __half2 b1 = __float22half2_rn(make_float2(v1[6], v1[7]));
            uint2 ua = make_uint2(*(unsigned*)&a0, *(unsigned*)&a1);
            uint2 ub = make_uint2(*(unsigned*)&b0, *(unsigned*)&b1);
            *(uint2*)&g_xwh[(size_t)(r0 + 1) * BN + tx * 4]      = ua;
            *(uint2*)&g_xwh[(size_t)(r0 + 1) * BN + 64 + tx * 4] = ub;
        }
    }
}

// ---------------- gather1 fused: aggregate + relu + (@W2Wfc) + dinv ------------
// h_row = relu( dinv_d*(sum_s xw[s]*dinv[s] + xw[d]*dinv[d]) + b1 )
// z'[d] = (h_row @ c2) * dinv_d          (fp16 xw rows; fp32 accumulation)
__global__ void gather1_kernel(const float* __restrict__ b1) {
    int w = (blockIdx.x * blockDim.x + threadIdx.x) >> 5;
    int lane = threadIdx.x & 31;
    if (w >= N_NODES) return;
    int beg = g_rowstart[w];
    int end = g_rowstart[w + 1];
    const int fo = 4 * lane;                    // this lane's feature offset

    float dself = g_dinv[w];
    float4 self = ldg_half4(&g_xwh[(size_t)w * HID_DIM + fo]);
    float4 acc;
    acc.x = self.x * dself; acc.y = self.y * dself;
    acc.z = self.z * dself; acc.w = self.w * dself;

    int e = beg;
    for (; e + 7 < end; e += 8) {
        int sI[8]; float dv[8]; float4 v[8];
        #pragma unroll
        for (int i = 0; i < 8; i++) sI[i] = __ldg(&g_csr[e + i]);
        #pragma unroll
        for (int i = 0; i < 8; i++) dv[i] = __ldg(&g_dinv[sI[i]]);
        #pragma unroll
        for (int i = 0; i < 8; i++) v[i] = ldg_half4(&g_xwh[(size_t)sI[i] * HID_DIM + fo]);
        #pragma unroll
        for (int i = 0; i < 8; i++) {
            acc.x = fmaf(v[i].x, dv[i], acc.x);
            acc.y = fmaf(v[i].y, dv[i], acc.y);
            acc.z = fmaf(v[i].z, dv[i], acc.z);
            acc.w = fmaf(v[i].w, dv[i], acc.w);
        }
    }
    for (; e < end; e++) {
        int s0 = __ldg(&g_csr[e]);
        float d0 = __ldg(&g_dinv[s0]);
        float4 v0 = ldg_half4(&g_xwh[(size_t)s0 * HID_DIM + fo]);
        acc.x = fmaf(v0.x, d0, acc.x); acc.y = fmaf(v0.y, d0, acc.y);
        acc.z = fmaf(v0.z, d0, acc.z); acc.w = fmaf(v0.w, d0, acc.w);
    }
    float4 bb = reinterpret_cast<const float4*>(b1)[lane];
    float4 r;
    r.x = fmaxf(fmaf(dself, acc.x, bb.x), 0.f);
    r.y = fmaxf(fmaf(dself, acc.y, bb.y), 0.f);
    r.z = fmaxf(fmaf(dself, acc.z, bb.z), 0.f);
    r.w = fmaxf(fmaf(dself, acc.w, bb.w), 0.f);

    // z = h_row @ c2 : lane covers features 4*lane..4*lane+3 -> c2[8*lane..+7]
    float4 ca = *(const float4*)&g_c2[8 * lane];       // (f0c0,f0c1,f1c0,f1c1)
    float4 cb = *(const float4*)&g_c2[8 * lane + 4];   // (f2c0,f2c1,f3c0,f3c1)
    float z0 = r.x * ca.x + r.y * ca.z + r.z * cb.x + r.w * cb.z;
    float z1 = r.x * ca.y + r.y * ca.w + r.z * cb.y + r.w * cb.w;
    #pragma unroll
    for (int off = 16; off > 0; off >>= 1) {
        z0 += __shfl_xor_sync(0xffffffff, z0, off);
        z1 += __shfl_xor_sync(0xffffffff, z1, off);
    }
    if (lane == 0)
        *(float2*)&g_z[w * 2] = make_float2(z0 * dself, z1 * dself);
}

// ---------------- gather2': tiny float2 aggregation + leaky --------------------
// out[d] = leaky( dinv_d * (sum_s z'[s] + z'[d]) + cbias )
__global__ void gather2_kernel(float* __restrict__ out) {
    int w = (blockIdx.x * blockDim.x + threadIdx.x) >> 5;
    int lane = threadIdx.x & 31;
    if (w >= N_NODES) return;
    int beg = g_rowstart[w];
    int end = g_rowstart[w + 1];

    float ax = 0.f, ay = 0.f;
    for (int e = beg + lane; e < end; e += 32) {
        int s = __ldg(&g_csr[e]);
        float2 v = *(const float2*)&g_z[s * 2];
        ax += v.x; ay += v.y;
    }
    #pragma unroll
    for (int off = 16; off > 0; off >>= 1) {
        ax += __shfl_xor_sync(0xffffffff, ax, off);
        ay += __shfl_xor_sync(0xffffffff, ay, off);
    }
    if (lane == 0) {
        float di = g_dinv[w];
        float2 zs = *(const float2*)&g_z[w * 2];
        float o0 = fmaf(di, ax + zs.x, g_cbias[0]);
        float o1 = fmaf(di, ay + zs.y, g_cbias[1]);
        out[w * 2 + 0] = (o0 > 0.f) ? o0 : 0.01f * o0;
        out[w * 2 + 1] = (o1 > 0.f) ? o1 : 0.01f * o1;
    }
}

// ---------------- launch -------------------------------------------------------
// Three arms: side stream (deg -> scan -> fill), wfc stream, default (gemm1).
// Join all before gather1.
extern "C" void kernel_launch(void* const* d_in, const int* in_sizes, int n_in,
                              void* d_out, int out_size) {
    const float* x   = (const float*)d_in[0];
    const int*   ei  = (const int*)d_in[1];   // JAX default: int64 demoted to int32
    const float* W1  = (const float*)d_in[2];
    const float* b1  = (const float*)d_in[3];
    const float* W2  = (const float*)d_in[4];
    const float* b2  = (const float*)d_in[5];
    const float* Wfc = (const float*)d_in[6];
    const float* bfc = (const float*)d_in[7];
    float* out = (float*)d_out;

    const int* src = ei;
    const int* dst = ei + N_EDGES;

    static cudaStream_t s_side = nullptr, s_w = nullptr;
    static cudaEvent_t  e_fork = nullptr, e_join = nullptr, e_wfc = nullptr;
    if (s_side == nullptr) {
        cudaStreamCreateWithFlags(&s_side, cudaStreamNonBlocking);
        cudaStreamCreateWithFlags(&s_w,    cudaStreamNonBlocking);
        cudaEventCreateWithFlags(&e_fork, cudaEventDisableTiming);
        cudaEventCreateWithFlags(&e_join, cudaEventDisableTiming);
        cudaEventCreateWithFlags(&e_wfc,  cudaEventDisableTiming);
    }

    // fork both side streams off the (captured) default stream
    cudaEventRecord(e_fork, 0);
    cudaStreamWaitEvent(s_side, e_fork, 0);
    cudaStreamWaitEvent(s_w,    e_fork, 0);

    // side stream: degree(+rank, +g_state reset) + scan(+dinv, +g_degi reset) + fill
    deg_kernel<<<(N_EDGES + 255) / 256, 256, 0, s_side>>>(dst);
    scan_kernel<<<SCAN_NB, SCAN_BS, 0, s_side>>>();
    fill_kernel<<<(N_EDGES / 4 + 255) / 256, 256, 0, s_side>>>(src, dst);
    cudaEventRecord(e_join, s_side);

    // wfc stream: tiny precompute, parallel to everything
    wfc_kernel<<<1, 128, 0, s_w>>>(W2, b2, Wfc, bfc);
    cudaEventRecord(e_wfc, s_w);

    // default stream: gemm1 (independent of degree chain), then join both
    gemm1_kernel<<<dim3(1, (N_NODES + 127) / 128), 256>>>(x, W1);
    cudaStreamWaitEvent(0, e_join, 0);
    cudaStreamWaitEvent(0, e_wfc, 0);

    // fused layer-1 aggregation + relu + (W2 Wfc) projection + dinv scale
    gather1_kernel<<<(N_NODES * 32 + 255) / 256, 256>>>(b1);

    // tiny layer-2 aggregation + FC bias + leaky relu
    gather2_kernel<<<(N_NODES * 32 + 255) / 256, 256>>>(out);
}

// round 15
// speedup vs baseline: 2.1046x; 1.1895x over previous
#include <cuda_runtime.h>
#include <cuda_fp16.h>
#include <cuda_bf16.h>
#include <mma.h>
#include <cstdint>

using namespace nvcuda;

#define N_NODES 50000
#define N_EDGES 800000
#define IN_DIM  128
#define HID_DIM 128
#define OUT_DIM 64

#define SCAN_BS   512
#define SCAN_NB   ((N_NODES + SCAN_BS - 1) / SCAN_BS)   // 98
#define BUILD_T   (SCAN_NB * SCAN_BS)                    // 50176 threads grid-wide

// ---------------- scratch (device globals: no allocation allowed) -------------
// Only referenced from DEVICE code (R5 lesson).
// Cross-call invariants (graph replays run the identical sequence):
//   g_degi  : zero at load; build phase-2 re-zeroes after reading.
//   g_state : build resets its own slot at kernel start (before barrier 1).
//   g_barctr/g_barrel : monotonic epoch barrier; never reset.
__device__ __align__(16) int                g_degi    [N_NODES];
__device__ __align__(16) float              g_dinv    [N_NODES];
__device__ __align__(16) int                g_rowstart[N_NODES + 1];
__device__ __align__(16) int                g_rank    [N_EDGES];
__device__ __align__(16) int                g_csr     [N_EDGES];
__device__ __align__(16) unsigned long long g_state   [SCAN_NB];
__device__ unsigned g_barctr[2];
__device__ unsigned g_barrel[2];
__device__ __align__(16) __half             g_xwh     [N_NODES * HID_DIM];  // x@W1, fp16
__device__ __align__(16) float              g_c2      [HID_DIM * 2];        // W2 @ Wfc
__device__ __align__(16) float              g_cbias   [2];                  // b2@Wfc + bfc
__device__ __align__(16) float              g_z       [N_NODES * 2];

// ---------------- helpers -------------------------------------------------------
__device__ __forceinline__ float4 ldg_half4(const __half* p) {
    uint2 u = __ldg(reinterpret_cast<const uint2*>(p));
    __half2 h0 = *reinterpret_cast<__half2*>(&u.x);
    __half2 h1 = *reinterpret_cast<__half2*>(&u.y);
    float2 f0 = __half22float2(h0);
    float2 f1 = __half22float2(h1);
    return make_float4(f0.x, f0.y, f1.x, f1.y);
}

// monotonic epoch grid barrier: replay-safe (no resets), deadlock-free for
// co-resident grids (98 blocks <= 148 SMs).
__device__ __forceinline__ void grid_barrier(int i) {
    __syncthreads();
    if (threadIdx.x == 0) {
        __threadfence();
        unsigned old = atomicAdd(&g_barctr[i], 1u);
        unsigned epoch = old / SCAN_NB;
        if (old % SCAN_NB == SCAN_NB - 1) {
            atomicAdd(&g_barrel[i], 1u);               // release this epoch
        } else {
            while (*(volatile unsigned*)&g_barrel[i] <= epoch) __nanosleep(64);
        }
        __threadfence();
    }
    __syncthreads();
}

// ---------------- build: deg -> barrier -> scan(+dinv) -> barrier -> fill ------
__global__ void __launch_bounds__(SCAN_BS, 1) build_kernel(
        const int* __restrict__ src, const int* __restrict__ dst) {
    int t = threadIdx.x, b = blockIdx.x;
    int gid = b * SCAN_BS + t;

    // reset this block's lookback state (used in phase 2, after barrier)
    if (t == 0) g_state[b] = 0ull;

    // phase 1: degree + per-edge rank (g_degi zeroed by previous call's phase 2)
    for (int e = gid; e < N_EDGES; e += BUILD_T) {
        unsigned d = (unsigned)__ldg(&dst[e]);
        g_rank[e] = (d < N_NODES) ? atomicAdd(&g_degi[d], 1) : 0;
    }
    grid_barrier(0);

    // phase 2: shfl-scan of degrees + dinv + re-zero degi; decoupled lookback
    __shared__ int warp_tot[16];
    __shared__ int s_excl;
    int lane = t & 31, wid = t >> 5;
    int i = gid;
    int s = (i < N_NODES) ? g_degi[i] : 0;
    if (i < N_NODES) {
        g_dinv[i] = rsqrtf((float)s + 1.0f);
        g_degi[i] = 0;                          // ready for next call
    }
    int v = s;
    #pragma unroll
    for (int off = 1; off < 32; off <<= 1) {
        int n = __shfl_up_sync(0xffffffff, v, off);
        if (lane >= off) v += n;
    }
    if (lane == 31) warp_tot[wid] = v;
    __syncthreads();
    if (wid == 0) {
        int wv = (lane < 16) ? warp_tot[lane] : 0;
        #pragma unroll
        for (int off = 1; off < 16; off <<= 1) {
            int n = __shfl_up_sync(0xffffffff, wv, off);
            if (lane >= off) wv += n;
        }
        if (lane < 16) warp_tot[lane] = wv;
    }
    __syncthreads();
    int incl = v + ((wid > 0) ? warp_tot[wid - 1] : 0);
    int total = warp_tot[15];

    if (t == 0) {
        if (b == 0) {
            atomicExch(&g_state[0], (2ull << 32) | (unsigned)total);
            s_excl = 0;
        } else {
            atomicExch(&g_state[b], (1ull << 32) | (unsigned)total);
            int excl = 0, idx = b - 1;
            while (true) {
                unsigned long long st = atomicAdd(&g_state[idx], 0ull);
                unsigned flag = (unsigned)(st >> 32);
                if (flag == 0u) { __nanosleep(20); continue; }
                excl += (int)(unsigned)st;
                if (flag == 2u) break;
                idx--;
            }
            atomicExch(&g_state[b], (2ull << 32) | (unsigned)(excl + total));
            s_excl = excl;
        }
    }
    __syncthreads();
    if (i < N_NODES) g_rowstart[i] = incl - s + s_excl;
    if (i == 0) g_rowstart[N_NODES] = N_EDGES;
    grid_barrier(1);

    // phase 3: atomic-free fill (16 contiguous edges/thread, int4 loads)
    int e0 = gid * 16;
    #pragma unroll
    for (int q = 0; q < 4; q++) {
        int e4 = e0 + q * 4;
        if (e4 + 3 < N_EDGES) {
            int4 d = *(const int4*)&dst[e4];
            int4 sv = *(const int4*)&src[e4];
            int4 r = *(const int4*)&g_rank[e4];
            if ((unsigned)d.x < N_NODES && (unsigned)sv.x < N_NODES)
                g_csr[g_rowstart[d.x] + r.x] = sv.x;
            if ((unsigned)d.y < N_NODES && (unsigned)sv.y < N_NODES)
                g_csr[g_rowstart[d.y] + r.y] = sv.y;
            if ((unsigned)d.z < N_NODES && (unsigned)sv.z < N_NODES)
                g_csr[g_rowstart[d.z] + r.z] = sv.z;
            if ((unsigned)d.w < N_NODES && (unsigned)sv.w < N_NODES)
                g_csr[g_rowstart[d.w] + r.w] = sv.w;
        } else {
            for (int e = e4; e < N_EDGES && e < e4 + 4; e++) {
                unsigned d = (unsigned)dst[e], sv = (unsigned)src[e];
                if (d < N_NODES && sv < N_NODES)
                    g_csr[g_rowstart[d] + g_rank[e]] = (int)sv;
            }
        }
    }
}

// ---------------- precompute c2 = W2 @ Wfc (coalesced), cbias ------------------
__global__ void wfc_kernel(const float* __restrict__ W2, const float* __restrict__ b2,
                           const float* __restrict__ Wfc, const float* __restrict__ bfc) {
    int tid = threadIdx.x;               // 512 threads
    int f = tid >> 2, j = tid & 3;       // 4 threads per feature
    float c0 = 0.f, c1 = 0.f;
    const float* wp = &W2[f * OUT_DIM + j * 16];
    #pragma unroll
    for (int q = 0; q < 4; q++) {
        float4 w = *(const float4*)&wp[q * 4];
        int kb = j * 16 + q * 4;
        c0 = fmaf(w.x, __ldg(&Wfc[(kb + 0) * 2 + 0]), c0);
        c1 = fmaf(w.x, __ldg(&Wfc[(kb + 0) * 2 + 1]), c1);
        c0 = fmaf(w.y, __ldg(&Wfc[(kb + 1) * 2 + 0]), c0);
        c1 = fmaf(w.y, __ldg(&Wfc[(kb + 1) * 2 + 1]), c1);
        c0 = fmaf(w.z, __ldg(&Wfc[(kb + 2) * 2 + 0]), c0);
        c1 = fmaf(w.z, __ldg(&Wfc[(kb + 2) * 2 + 1]), c1);
        c0 = fmaf(w.w, __ldg(&Wfc[(kb + 3) * 2 + 0]), c0);
        c1 = fmaf(w.w, __ldg(&Wfc[(kb + 3) * 2 + 1]), c1);
    }
    c0 += __shfl_xor_sync(0xffffffff, c0, 1);
    c0 += __shfl_xor_sync(0xffffffff, c0, 2);
    c1 += __shfl_xor_sync(0xffffffff, c1, 1);
    c1 += __shfl_xor_sync(0xffffffff, c1, 2);
    if (j == 0) {
        g_c2[f * 2 + 0] = c0;
        g_c2[f * 2 + 1] = c1;
    }
    if (tid < 2) {
        float acc = bfc[tid];
        for (int k = 0; k < OUT_DIM; k++) acc = fmaf(b2[k], Wfc[k * 2 + tid], acc);
        g_cbias[tid] = acc;
    }
}

// ---------------- gemm1: wmma fp16 (fp32 accum), 128x128 tile ------------------
// smem: Ah[128][136] fp16 (34816B) + Bh[128][136] fp16 (34816B) = 69632B dynamic;
// epilogue reuses smem as C float [128][128] (65536B).
#define GLDA 136
__global__ void __launch_bounds__(256, 1) gemm1_kernel(
        const float* __restrict__ x, const float* __restrict__ W1) {
    extern __shared__ char smem[];
    __half* Ah = (__half*)smem;
    __half* Bh = (__half*)(smem + 128 * GLDA * 2);
    float*  Cs = (float*)smem;

    const int tid = threadIdx.x;         // 256
    const int row0 = blockIdx.x * 128;

    // load + convert A (x tile) and B (W1) : 16384 elems each, 64/thread
    #pragma unroll
    for (int l = 0; l < 16; l++) {
        int idx = (tid + l * 256) * 4;   // float4 granularity
        int r = idx >> 7, c = idx & 127;
        float4 fa = make_float4(0.f, 0.f, 0.f, 0.f);
        if (row0 + r < N_NODES) fa = *(const float4*)&x[(size_t)(row0 + r) * 128 + c];
        __half2 a0 = __float22half2_rn(make_float2(fa.x, fa.y));
        __half2 a1 = __float22half2_rn(make_float2(fa.z, fa.w));
        *(uint2*)&Ah[r * GLDA + c] = make_uint2(*(unsigned*)&a0, *(unsigned*)&a1);
        float4 fb = *(const float4*)&W1[(size_t)r * 128 + c];
        __half2 b0 = __float22half2_rn(make_float2(fb.x, fb.y));
        __half2 b1 = __float22half2_rn(make_float2(fb.z, fb.w));
        *(uint2*)&Bh[r * GLDA + c] = make_uint2(*(unsigned*)&b0, *(unsigned*)&b1);
    }
    __syncthreads();

    // warp grid 2(M) x 4(N): each warp 64 rows x 32 cols
    const int wid = tid >> 5;
    const int wm = wid & 1, wn = wid >> 1;
    wmma::fragment<wmma::accumulator, 16, 16, 16, float> acc[4][2];
    #pragma unroll
    for (int i = 0; i < 4; i++)
        #pragma unroll
        for (int j = 0; j < 2; j++)
            wmma::fill_fragment(acc[i][j], 0.f);

    #pragma unroll
    for (int k = 0; k < 8; k++) {
        wmma::fragment<wmma::matrix_a, 16, 16, 16, __half, wmma::row_major> af[4];
        wmma::fragment<wmma::matrix_b, 16, 16, 16, __half, wmma::row_major> bf[2];
        #pragma unroll
        for (int i = 0; i < 4; i++)
            wmma::load_matrix_sync(af[i], Ah + (wm * 64 + i * 16) * GLDA + k * 16, GLDA);
        #pragma unroll
        for (int j = 0; j < 2; j++)
            wmma::load_matrix_sync(bf[j], Bh + (k * 16) * GLDA + wn * 32 + j * 16, GLDA);
        #pragma unroll
        for (int i = 0; i < 4; i++)
            #pragma unroll
            for (int j = 0; j < 2; j++)
                wmma::mma_sync(acc[i][j], af[i], bf[j], acc[i][j]);
    }
    __syncthreads();   // done reading Ah/Bh; reuse smem as C

    #pragma unroll
    for (int i = 0; i < 4; i++)
        #pragma unroll
        for (int j = 0; j < 2; j++)
            wmma::store_matrix_sync(Cs + (wm * 64 + i * 16) * 128 + wn * 32 + j * 16,
                                    acc[i][j], 128, wmma::mem_row_major);
    __syncthreads();

    // write out fp16
    #pragma unroll
    for (int l = 0; l < 16; l++) {
        int idx = (tid + l * 256) * 4;
        int r = idx >> 7, c = idx & 127;
        if (row0 + r < N_NODES) {
            float4 f = *(const float4*)&Cs[r * 128 + c];
            __half2 h0 = __float22half2_rn(make_float2(f.x, f.y));
            __half2 h1 = __float22half2_rn(make_float2(f.z, f.w));
            *(uint2*)&g_xwh[(size_t)(row0 + r) * 128 + c] =
                make_uint2(*(unsigned*)&h0, *(unsigned*)&h1);
        }
    }
}

// ---------------- gather1 fused: aggregate + relu + (@W2Wfc) + dinv ------------
__global__ void gather1_kernel(const float* __restrict__ b1) {
    int w = (blockIdx.x * blockDim.x + threadIdx.x) >> 5;
    int lane = threadIdx.x & 31;
    if (w >= N_NODES) return;
    int beg = g_rowstart[w];
    int end = g_rowstart[w + 1];
    const int fo = 4 * lane;

    float dself = g_dinv[w];
    float4 self = ldg_half4(&g_xwh[(size_t)w * HID_DIM + fo]);
    float4 acc;
    acc.x = self.x * dself; acc.y = self.y * dself;
    acc.z = self.z * dself; acc.w = self.w * dself;

    int e = beg;
    for (; e + 7 < end; e += 8) {
        int sI[8]; float dv[8]; float4 v[8];
        #pragma unroll
        for (int i = 0; i < 8; i++) sI[i] = __ldg(&g_csr[e + i]);
        #pragma unroll
        for (int i = 0; i < 8; i++) dv[i] = __ldg(&g_dinv[sI[i]]);
        #pragma unroll
        for (int i = 0; i < 8; i++) v[i] = ldg_half4(&g_xwh[(size_t)sI[i] * HID_DIM + fo]);
        #pragma unroll
        for (int i = 0; i < 8; i++) {
            acc.x = fmaf(v[i].x, dv[i], acc.x);
            acc.y = fmaf(v[i].y, dv[i], acc.y);
            acc.z = fmaf(v[i].z, dv[i], acc.z);
            acc.w = fmaf(v[i].w, dv[i], acc.w);
        }
    }
    for (; e < end; e++) {
        int s0 = __ldg(&g_csr[e]);
        float d0 = __ldg(&g_dinv[s0]);
        float4 v0 = ldg_half4(&g_xwh[(size_t)s0 * HID_DIM + fo]);
        acc.x = fmaf(v0.x, d0, acc.x); acc.y = fmaf(v0.y, d0, acc.y);
        acc.z = fmaf(v0.z, d0, acc.z); acc.w = fmaf(v0.w, d0, acc.w);
    }
    float4 bb = reinterpret_cast<const float4*>(b1)[lane];
    float4 r;
    r.x = fmaxf(fmaf(dself, acc.x, bb.x), 0.f);
    r.y = fmaxf(fmaf(dself, acc.y, bb.y), 0.f);
    r.z = fmaxf(fmaf(dself, acc.z, bb.z), 0.f);
    r.w = fmaxf(fmaf(dself, acc.w, bb.w), 0.f);

    float4 ca = *(const float4*)&g_c2[8 * lane];
    float4 cb = *(const float4*)&g_c2[8 * lane + 4];
    float z0 = r.x * ca.x + r.y * ca.z + r.z * cb.x + r.w * cb.z;
    float z1 = r.x * ca.y + r.y * ca.w + r.z * cb.y + r.w * cb.w;
    #pragma unroll
    for (int off = 16; off > 0; off >>= 1) {
        z0 += __shfl_xor_sync(0xffffffff, z0, off);
        z1 += __shfl_xor_sync(0xffffffff, z1, off);
    }
    if (lane == 0)
        *(float2*)&g_z[w * 2] = make_float2(z0 * dself, z1 * dself);
}

// ---------------- gather2': tiny float2 aggregation + leaky --------------------
__global__ void gather2_kernel(float* __restrict__ out) {
    int w = (blockIdx.x * blockDim.x + threadIdx.x) >> 5;
    int lane = threadIdx.x & 31;
    if (w >= N_NODES) return;
    int beg = g_rowstart[w];
    int end = g_rowstart[w + 1];

    float ax = 0.f, ay = 0.f;
    for (int e = beg + lane; e < end; e += 32) {
        int s = __ldg(&g_csr[e]);
        float2 v = *(const float2*)&g_z[s * 2];
        ax += v.x; ay += v.y;
    }
    #pragma unroll
    for (int off = 16; off > 0; off >>= 1) {
        ax += __shfl_xor_sync(0xffffffff, ax, off);
        ay += __shfl_xor_sync(0xffffffff, ay, off);
    }
    if (lane == 0) {
        float di = g_dinv[w];
        float2 zs = *(const float2*)&g_z[w * 2];
        float o0 = fmaf(di, ax + zs.x, g_cbias[0]);
        float o1 = fmaf(di, ay + zs.y, g_cbias[1]);
        out[w * 2 + 0] = (o0 > 0.f) ? o0 : 0.01f * o0;
        out[w * 2 + 1] = (o1 > 0.f) ? o1 : 0.01f * o1;
    }
}

// ---------------- launch -------------------------------------------------------
// Arms: s_side = build (one persistent kernel), s_w = wfc, default = gemm1.
extern "C" void kernel_launch(void* const* d_in, const int* in_sizes, int n_in,
                              void* d_out, int out_size) {
    const float* x   = (const float*)d_in[0];
    const int*   ei  = (const int*)d_in[1];   // JAX default: int64 demoted to int32
    const float* W1  = (const float*)d_in[2];
    const float* b1  = (const float*)d_in[3];
    const float* W2  = (const float*)d_in[4];
    const float* b2  = (const float*)d_in[5];
    const float* Wfc = (const float*)d_in[6];
    const float* bfc = (const float*)d_in[7];
    float* out = (float*)d_out;

    const int* src = ei;
    const int* dst = ei + N_EDGES;

    static cudaStream_t s_side = nullptr, s_w = nullptr;
    static cudaEvent_t  e_fork = nullptr, e_join = nullptr, e_wfc = nullptr;
    if (s_side == nullptr) {
        cudaStreamCreateWithFlags(&s_side, cudaStreamNonBlocking);
        cudaStreamCreateWithFlags(&s_w,    cudaStreamNonBlocking);
        cudaEventCreateWithFlags(&e_fork, cudaEventDisableTiming);
        cudaEventCreateWithFlags(&e_join, cudaEventDisableTiming);
        cudaEventCreateWithFlags(&e_wfc,  cudaEventDisableTiming);
        cudaFuncSetAttribute(gemm1_kernel,
                             cudaFuncAttributeMaxDynamicSharedMemorySize,
                             128 * GLDA * 2 * 2);      // 69632 B
    }
    const int GEMM_SMEM = 128 * GLDA * 2 * 2;

    // fork side streams off the (captured) default stream
    cudaEventRecord(e_fork, 0);
    cudaStreamWaitEvent(s_side, e_fork, 0);
    cudaStreamWaitEvent(s_w,    e_fork, 0);

    // side stream: one persistent CSR-build kernel (submitted first)
    build_kernel<<<SCAN_NB, SCAN_BS, 0, s_side>>>(src, dst);
    cudaEventRecord(e_join, s_side);

    // wfc stream: tiny precompute
    wfc_kernel<<<1, 512, 0, s_w>>>(W2, b2, Wfc, bfc);
    cudaEventRecord(e_wfc, s_w);

    // default stream: tensor-core gemm1
    gemm1_kernel<<<(N_NODES + 127) / 128, 256, GEMM_SMEM>>>(x, W1);
    cudaStreamWaitEvent(0, e_join, 0);
    cudaStreamWaitEvent(0, e_wfc, 0);

    // fused layer-1 aggregation + relu + (W2 Wfc) projection + dinv scale
    gather1_kernel<<<(N_NODES * 32 + 255) / 256, 256>>>(b1);

    // tiny layer-2 aggregation + FC bias + leaky relu
    gather2_kernel<<<(N_NODES * 32 + 255) / 256, 256>>>(out);
}